// round 8
// baseline (speedup 1.0000x reference)
#include <cuda_runtime.h>
#include <cuda_bf16.h>
#include <math.h>

#define NN 32768
#define EE 131072
#define HH 6
#define CC 128
#define LL 6
#define GG 2048
#define PC 768      // p / y width (H*C)
#define KB 896      // gemm B K dim (768 y + 128 x)

// ---------------- scratch (device globals) -----------------------------------
__device__ float g_x[NN*CC];
__device__ float g_xn[NN*CC];
__device__ __nv_bfloat16 g_xh[NN*CC];
__device__ __nv_bfloat16 g_xl[NN*CC];
__device__ __nv_bfloat16 g_pb[NN*PC];       // p, bf16, 1/sqrt(C) folded
__device__ __nv_bfloat16 g_yh[NN*PC];
__device__ __nv_bfloat16 g_yl[NN*PC];
__device__ __nv_bfloat16 g_WAh[LL*PC*CC];   // Wqk = Wk^T Wq per head, bf16
__device__ float g_bqk[LL*PC];
__device__ __nv_bfloat16 g_WBh[LL*CC*KB];   // [Wv/H | Ws^T] combined, bf16 hi
__device__ __nv_bfloat16 g_WBl[LL*CC*KB];
__device__ float g_bvm[LL*CC];              // mean_h bv
__device__ int   g_deg[NN];
__device__ int   g_cnt[NN];
__device__ int   g_off[NN+1];
__device__ int   g_srcs[EE];                // CSR-ordered source node ids
__device__ float g_m1[GG*CC];
__device__ float g_m2[GG*CC];

// ---------------- prep: fold weights + zero counters (single launch) ---------
__global__ void prep_kernel(
    const float* __restrict__ Wq, const float* __restrict__ Wk,
    const float* __restrict__ Wv, const float* __restrict__ Ws,
    const float* __restrict__ bq, const float* __restrict__ bv)
{
    int bid = blockIdx.x, tid = threadIdx.x;
    if(bid < 4608){
        // Wqk_h[c,c2] = sum_cc Wk[h*128+cc, c] * Wq[h*128+cc, c2]
        int l = bid / (HH*CC);
        int rem = bid % (HH*CC);
        int h = rem >> 7, c = rem & 127;
        __shared__ float wk[128];
        wk[tid] = Wk[((size_t)l*PC + h*CC + tid)*CC + c];
        __syncthreads();
        float acc = 0.f;
        const float* wqp = &Wq[((size_t)l*PC + h*CC)*CC + tid];
        #pragma unroll 8
        for(int cc=0; cc<CC; cc++) acc += wk[cc] * wqp[(size_t)cc*CC];
        g_WAh[((size_t)l*PC + h*CC + c)*CC + tid] = __float2bfloat16(acc);
    } else if(bid < 4644){
        int b2 = bid - 4608;
        int l = b2 / HH, h = b2 % HH;
        float acc = 0.f;
        for(int cc=0; cc<CC; cc++)
            acc += bq[l*PC + h*CC + cc] * Wk[((size_t)l*PC + h*CC + cc)*CC + tid];
        g_bqk[l*PC + h*CC + tid] = acc;
    } else if(bid < 10020){
        int idx = (bid-4644)*128 + tid;          // over LL*CC*KB
        int l = idx / (CC*KB);
        int j = (idx / KB) % CC;
        int c = idx % KB;
        float v;
        if(c < PC){
            int h = c >> 7, cp = c & 127;
            v = Wv[((size_t)l*PC + h*CC + j)*CC + cp] * (1.f/HH);
        } else {
            v = Ws[((size_t)l*CC + j)*CC + (c - PC)];
        }
        size_t o = ((size_t)l*CC + j)*KB + c;
        __nv_bfloat16 hi = __float2bfloat16(v);
        g_WBh[o] = hi;
        g_WBl[o] = __float2bfloat16(v - __bfloat162float(hi));
    } else if(bid < 10276){
        int i = (bid-10020)*128 + tid;
        g_deg[i]=0; g_cnt[i]=0;
    } else {
        int i = (bid-10276)*128 + tid;           // LL*CC
        int l = i >> 7, j = i & 127;
        float a = 0.f;
        #pragma unroll
        for(int h=0;h<HH;h++) a += bv[l*PC + h*CC + j];
        g_bvm[i] = a * (1.f/HH);
    }
}

// ---------------- CSR build --------------------------------------------------
__global__ void hist_kernel(const int* __restrict__ dst){
    int e = blockIdx.x*blockDim.x + threadIdx.x;
    if(e < EE) atomicAdd(&g_deg[dst[e]], 1);
}
__global__ void scan_kernel(){
    __shared__ int sh[1024];
    __shared__ int sbase;
    int tid = threadIdx.x;
    if(tid==0){ sbase = 0; g_off[0] = 0; }
    __syncthreads();
    for(int chunk=0; chunk<NN/1024; chunk++){
        int idx = chunk*1024 + tid;
        sh[tid] = g_deg[idx];
        __syncthreads();
        for(int o=1;o<1024;o<<=1){
            int t = (tid>=o) ? sh[tid-o] : 0;
            __syncthreads();
            sh[tid] += t;
            __syncthreads();
        }
        g_off[idx+1] = sbase + sh[tid];
        __syncthreads();
        if(tid==1023) sbase += sh[1023];
        __syncthreads();
    }
}
__global__ void scatter_kernel(const int* __restrict__ src, const int* __restrict__ dst){
    int e = blockIdx.x*blockDim.x + threadIdx.x;
    if(e < EE){
        int d = dst[e];
        int pos = g_off[d] + atomicAdd(&g_cnt[d], 1);
        g_srcs[pos] = src[e];
    }
}

// ---------------- embedding (+ bf16 split) -----------------------------------
__global__ void embed_kernel(const int* __restrict__ atoms, const float* __restrict__ embd){
    int i = blockIdx.x*blockDim.x + threadIdx.x;
    int n = i >> 7, c = i & 127;
    float v = embd[atoms[n]*CC + c];
    g_x[i] = v;
    __nv_bfloat16 h = __float2bfloat16(v);
    g_xh[i] = h;
    g_xl[i] = __float2bfloat16(v - __bfloat162float(h));
}

// ---------------- MMA / LDSM / cp.async macros --------------------------------
#define MMA16816(d, a, b) asm volatile( \
    "mma.sync.aligned.m16n8k16.row.col.f32.bf16.bf16.f32 " \
    "{%0,%1,%2,%3}, {%4,%5,%6,%7}, {%8,%9}, {%0,%1,%2,%3};" \
    : "+f"(d[0]),"+f"(d[1]),"+f"(d[2]),"+f"(d[3]) \
    : "r"(a[0]),"r"(a[1]),"r"(a[2]),"r"(a[3]), "r"(b[0]),"r"(b[1]))

#define LDSM_X4(R0,R1,R2,R3,A) asm volatile( \
    "ldmatrix.sync.aligned.m8n8.x4.shared.b16 {%0,%1,%2,%3}, [%4];" \
    : "=r"(R0),"=r"(R1),"=r"(R2),"=r"(R3) : "r"(A))

#define CPASYNC16(saddr, gptr) asm volatile( \
    "cp.async.cg.shared.global [%0], [%1], 16;" :: "r"(saddr), "l"(gptr))
#define CPCOMMIT() asm volatile("cp.async.commit_group;" ::: "memory")
#define CPWAIT(n)  asm volatile("cp.async.wait_group %0;" :: "n"(n) : "memory")

__device__ __forceinline__ unsigned smem_u32p(const void* p){
    return (unsigned)__cvta_generic_to_shared(p);
}

// ---------------- GEMM A: p = (x @ Wqk^T + bqk)/sqrt(C), 128x128 tiles -------
// Full K=128 resident in smem; one cp.async load phase, one barrier, 8 MMA steps.
#define GP_STRIDE 136
#define GP_ASZ (128*GP_STRIDE*2)     // 34816 B
#define GP_SMEM (2*GP_ASZ)           // 69632 B
__global__ __launch_bounds__(256,2) void gemm_p(int layer)
{
    extern __shared__ char dsm[];
    __nv_bfloat16 (*sA)[GP_STRIDE] = (__nv_bfloat16(*)[GP_STRIDE])(dsm);
    __nv_bfloat16 (*sB)[GP_STRIDE] = (__nv_bfloat16(*)[GP_STRIDE])(dsm + GP_ASZ);
    int col0 = blockIdx.x * 128;
    int row0 = blockIdx.y * 128;
    int tid = threadIdx.x, warp = tid >> 5, lane = tid & 31;
    int wm = warp >> 2, wn = warp & 3;      // 2 x 4 warp grid
    int wr0 = wm * 64, wc0 = wn * 32;       // warp tile 64 x 32
    int gid = lane >> 2, tig = lane & 3;

    float acc[4][4][4];
    #pragma unroll
    for(int i=0;i<4;i++)
        #pragma unroll
        for(int j=0;j<4;j++)
            #pragma unroll
            for(int t=0;t<4;t++) acc[i][j][t] = 0.f;

    int lr = tid >> 1;              // 0..127
    int lc = (tid & 1) * 64;        // 0 or 64: 8 uint4 per thread per tile
    const __nv_bfloat16* Ag = &g_xh[(size_t)(row0+lr)*CC + lc];
    const __nv_bfloat16* Bg = &g_WAh[((size_t)layer*PC + col0 + lr)*CC + lc];
    unsigned dA = smem_u32p(&sA[lr][lc]);
    unsigned dB = smem_u32p(&sB[lr][lc]);
    #pragma unroll
    for(int q=0;q<8;q++){
        CPASYNC16(dA + q*16, Ag + 8*q);
        CPASYNC16(dB + q*16, Bg + 8*q);
    }
    CPCOMMIT();

    unsigned aAddr[4], bAddr[2];
    #pragma unroll
    for(int i=0;i<4;i++)
        aAddr[i] = smem_u32p(&sA[wr0 + i*16 + (lane & 15)][(lane >> 4) * 8]);
    #pragma unroll
    for(int g=0; g<2; g++)
        bAddr[g] = smem_u32p(&sB[wc0 + g*16 + (lane & 7) + ((lane >> 4) << 3)][((lane >> 3) & 1) * 8]);

    CPWAIT(0);
    __syncthreads();

    #pragma unroll
    for(int ks=0; ks<128; ks+=16){
        unsigned a_[4][4], b_[4][2];
        #pragma unroll
        for(int i=0;i<4;i++)
            LDSM_X4(a_[i][0], a_[i][1], a_[i][2], a_[i][3], aAddr[i] + ks*2);
        #pragma unroll
        for(int g=0; g<2; g++)
            LDSM_X4(b_[g*2][0], b_[g*2][1], b_[g*2+1][0], b_[g*2+1][1], bAddr[g] + ks*2);
        #pragma unroll
        for(int i=0;i<4;i++)
            #pragma unroll
            for(int j=0;j<4;j++)
                MMA16816(acc[i][j], a_[i], b_[j]);
    }

    const float invsq = 0.08838834764831845f;  // 1/sqrt(128)
    #pragma unroll
    for(int i=0;i<4;i++){
        int r = row0 + wr0 + i*16 + gid;
        #pragma unroll
        for(int j=0;j<4;j++){
            int c = col0 + wc0 + j*8 + 2*tig;
            float b0 = g_bqk[layer*PC + c], b1 = g_bqk[layer*PC + c + 1];
            *(__nv_bfloat162*)&g_pb[(size_t)r*PC + c] = __nv_bfloat162(
                __float2bfloat16((acc[i][j][0] + b0)*invsq),
                __float2bfloat16((acc[i][j][1] + b1)*invsq));
            *(__nv_bfloat162*)&g_pb[(size_t)(r+8)*PC + c] = __nv_bfloat162(
                __float2bfloat16((acc[i][j][2] + b0)*invsq),
                __float2bfloat16((acc[i][j][3] + b1)*invsq));
        }
    }
}

// ---------------- attention: single-pass online softmax, aggregate x ---------
__global__ __launch_bounds__(256) void attn_kernel(int parity)
{
    const float4* x4 = (const float4*)(parity ? g_xn : g_x);
    int warp = (blockIdx.x*blockDim.x + threadIdx.x) >> 5;
    int lane = threadIdx.x & 31;
    if(warp >= NN) return;
    int d = warp;

    const __nv_bfloat162* pb = (const __nv_bfloat162*)&g_pb[(size_t)d*PC];
    float4 p[HH];
    #pragma unroll
    for(int h=0;h<HH;h++){
        float2 f0 = __bfloat1622float2(pb[h*64 + lane*2]);
        float2 f1 = __bfloat1622float2(pb[h*64 + lane*2 + 1]);
        p[h] = make_float4(f0.x, f0.y, f1.x, f1.y);
    }

    int e0 = g_off[d], e1 = g_off[d+1];
    float m[HH], den[HH];
    float4 y[HH];
    #pragma unroll
    for(int h=0;h<HH;h++){ m[h]=-1e30f; den[h]=0.f; y[h]=make_float4(0.f,0.f,0.f,0.f); }

    for(int t=e0; t<e1; t++){
        int s = g_srcs[t];
        float4 xv = x4[(size_t)s*32 + lane];
        float dot[HH];
        #pragma unroll
        for(int h=0;h<HH;h++)
            dot[h] = p[h].x*xv.x + p[h].y*xv.y + p[h].z*xv.z + p[h].w*xv.w;
        #pragma unroll
        for(int h=0;h<HH;h++){
            #pragma unroll
            for(int o=16;o>0;o>>=1) dot[h] += __shfl_xor_sync(0xffffffffu, dot[h], o);
        }
        #pragma unroll
        for(int h=0;h<HH;h++){
            float mn = fmaxf(m[h], dot[h]);
            float corr = __expf(m[h] - mn);
            float ex   = __expf(dot[h] - mn);
            den[h] = den[h]*corr + ex;
            y[h].x = y[h].x*corr + ex*xv.x;
            y[h].y = y[h].y*corr + ex*xv.y;
            y[h].z = y[h].z*corr + ex*xv.z;
            y[h].w = y[h].w*corr + ex*xv.w;
            m[h] = mn;
        }
    }

    size_t base = (size_t)d*PC;
    #pragma unroll
    for(int h=0;h<HH;h++){
        float r = (den[h] > 0.f) ? 1.f/den[h] : 0.f;
        float v0=y[h].x*r, v1=y[h].y*r, v2=y[h].z*r, v3=y[h].w*r;
        int c = h*CC + lane*4;
        __nv_bfloat16 h0=__float2bfloat16(v0), h1=__float2bfloat16(v1);
        __nv_bfloat16 h2=__float2bfloat16(v2), h3=__float2bfloat16(v3);
        *(__nv_bfloat162*)&g_yh[base+c]   = __nv_bfloat162(h0, h1);
        *(__nv_bfloat162*)&g_yh[base+c+2] = __nv_bfloat162(h2, h3);
        __nv_bfloat16 l0=__float2bfloat16(v0-__bfloat162float(h0));
        __nv_bfloat16 l1=__float2bfloat16(v1-__bfloat162float(h1));
        __nv_bfloat16 l2=__float2bfloat16(v2-__bfloat162float(h2));
        __nv_bfloat16 l3=__float2bfloat16(v3-__bfloat162float(h3));
        *(__nv_bfloat162*)&g_yl[base+c]   = __nv_bfloat162(l0, l1);
        *(__nv_bfloat162*)&g_yl[base+c+2] = __nv_bfloat162(l2, l3);
    }
}

// ---------------- GEMM B: out = [y|x] @ WB^T (+bias,+res) -> LN -> ReLU ------
// 128x128 tile, K=896 in 14 chunks of 64; 3-pass hi/lo; DOUBLE-BUFFERED
// cp.async pipeline. smem: 2 stages x (Ah|Al|Bh|Bl each 128x72 bf16).
#define GB_SEG 18432
#define GB_STAGE (4*GB_SEG)          // 73728
#define GB_SMEM (2*GB_STAGE)         // 147456
__global__ __launch_bounds__(256) void gemm_b(
    int layer, int parity,
    const float* __restrict__ bs, const float* __restrict__ lg, const float* __restrict__ lb)
{
    extern __shared__ char dsm[];
    __nv_bfloat16 (*Ah)[72] = (__nv_bfloat16(*)[72])(dsm);
    __nv_bfloat16 (*Al)[72] = (__nv_bfloat16(*)[72])(dsm + GB_SEG);
    __nv_bfloat16 (*Bh)[72] = (__nv_bfloat16(*)[72])(dsm + 2*GB_SEG);
    __nv_bfloat16 (*Bl)[72] = (__nv_bfloat16(*)[72])(dsm + 3*GB_SEG);

    const float* xold = parity ? g_xn : g_x;
    float*       xo   = parity ? g_x  : g_xn;
    int row0 = blockIdx.x * 128;
    int tid = threadIdx.x, warp = tid >> 5, lane = tid & 31;
    int wm = warp >> 2, wn = warp & 3;
    int wr0 = wm * 64, wc0 = wn * 32;
    int gid = lane >> 2, tig = lane & 3;

    float acc[4][4][4];
    #pragma unroll
    for(int i=0;i<4;i++)
        #pragma unroll
        for(int j=0;j<4;j++)
            #pragma unroll
            for(int t=0;t<4;t++) acc[i][j][t] = 0.f;

    int lr = tid >> 1;
    int lc = (tid & 1) * 32;
    unsigned stAh = smem_u32p(&Ah[lr][lc]);
    unsigned stAl = smem_u32p(&Al[lr][lc]);
    unsigned stBh = smem_u32p(&Bh[lr][lc]);
    unsigned stBl = smem_u32p(&Bl[lr][lc]);

    unsigned aAddrH[4], aAddrL[4], bAddrH[2], bAddrL[2];
    {
        int arow = lane & 15, ak = (lane >> 4) * 8;
        #pragma unroll
        for(int i=0;i<4;i++){
            aAddrH[i] = smem_u32p(&Ah[wr0 + i*16 + arow][ak]);
            aAddrL[i] = smem_u32p(&Al[wr0 + i*16 + arow][ak]);
        }
        int bcol = (lane & 7) + ((lane >> 4) << 3);
        int bk = ((lane >> 3) & 1) * 8;
        #pragma unroll
        for(int g=0; g<2; g++){
            bAddrH[g] = smem_u32p(&Bh[wc0 + g*16 + bcol][bk]);
            bAddrL[g] = smem_u32p(&Bl[wc0 + g*16 + bcol][bk]);
        }
    }

    // stage issue: 16 cp.async of 16B per thread
    auto issue = [&](int s){
        int k0 = s * 64;
        unsigned so = (unsigned)(s & 1) * GB_STAGE;
        const __nv_bfloat16 *ah, *al;
        if(k0 < PC){
            ah = &g_yh[(size_t)(row0+lr)*PC + k0 + lc];
            al = &g_yl[(size_t)(row0+lr)*PC + k0 + lc];
        } else {
            ah = &g_xh[(size_t)(row0+lr)*CC + (k0 - PC) + lc];
            al = &g_xl[(size_t)(row0+lr)*CC + (k0 - PC) + lc];
        }
        const __nv_bfloat16* bhg = &g_WBh[((size_t)layer*CC + lr)*KB + k0 + lc];
        const __nv_bfloat16* blg = &g_WBl[((size_t)layer*CC + lr)*KB + k0 + lc];
        #pragma unroll
        for(int q=0;q<4;q++){
            CPASYNC16(stAh + so + q*16, ah + 8*q);
            CPASYNC16(stAl + so + q*16, al + 8*q);
            CPASYNC16(stBh + so + q*16, bhg + 8*q);
            CPASYNC16(stBl + so + q*16, blg + 8*q);
        }
        CPCOMMIT();
    };

    issue(0);
    for(int s=0; s<14; s++){
        if(s < 13){ issue(s+1); CPWAIT(1); }
        else      { CPWAIT(0); }
        __syncthreads();
        unsigned bo = (unsigned)(s & 1) * GB_STAGE;

        #pragma unroll
        for(int ks=0; ks<64; ks+=16){
            unsigned bh_[4][2], bl_[4][2], a_[4][4];
            #pragma unroll
            for(int g=0; g<2; g++){
                LDSM_X4(bh_[g*2][0], bh_[g*2][1], bh_[g*2+1][0], bh_[g*2+1][1], bAddrH[g] + bo + ks*2);
                LDSM_X4(bl_[g*2][0], bl_[g*2][1], bl_[g*2+1][0], bl_[g*2+1][1], bAddrL[g] + bo + ks*2);
            }
            #pragma unroll
            for(int i=0;i<4;i++)
                LDSM_X4(a_[i][0], a_[i][1], a_[i][2], a_[i][3], aAddrH[i] + bo + ks*2);
            #pragma unroll
            for(int i=0;i<4;i++)
                #pragma unroll
                for(int j=0;j<4;j++){
                    MMA16816(acc[i][j], a_[i], bh_[j]);
                    MMA16816(acc[i][j], a_[i], bl_[j]);
                }
            #pragma unroll
            for(int i=0;i<4;i++)
                LDSM_X4(a_[i][0], a_[i][1], a_[i][2], a_[i][3], aAddrL[i] + bo + ks*2);
            #pragma unroll
            for(int i=0;i<4;i++)
                #pragma unroll
                for(int j=0;j<4;j++)
                    MMA16816(acc[i][j], a_[i], bh_[j]);
        }
        __syncthreads();
    }

    // dump accumulators to smem C (stride 132 floats)
    float* Csm = (float*)dsm;
    #pragma unroll
    for(int i=0;i<4;i++){
        int r = wr0 + i*16 + gid;
        #pragma unroll
        for(int j=0;j<4;j++){
            int c = wc0 + j*8 + 2*tig;
            Csm[r*132 + c]       = acc[i][j][0];
            Csm[r*132 + c + 1]   = acc[i][j][1];
            Csm[(r+8)*132 + c]   = acc[i][j][2];
            Csm[(r+8)*132 + c+1] = acc[i][j][3];
        }
    }
    __syncthreads();

    // epilogue: 2 threads per row, 64 channels each
    {
        int row = tid >> 1, half = tid & 1;
        int n = row0 + row;
        float* Crow = Csm + row*132 + half*64;
        float flag = (g_off[n+1] > g_off[n]) ? 1.f : 0.f;
        const float* xr = &xold[(size_t)n*CC + half*64];
        int cb = half*64;
        float s1 = 0.f;
        #pragma unroll 8
        for(int k=0;k<64;k++){
            int c = cb + k;
            float v = Crow[k] + bs[c] + flag*g_bvm[layer*CC + c] + xr[k];
            Crow[k] = v;
            s1 += v;
        }
        s1 += __shfl_xor_sync(0xffffffffu, s1, 1);
        float mean = s1 * (1.f/CC);
        float s2 = 0.f;
        #pragma unroll 8
        for(int k=0;k<64;k++){ float dv = Crow[k]-mean; s2 += dv*dv; }
        s2 += __shfl_xor_sync(0xffffffffu, s2, 1);
        float inv = rsqrtf(s2*(1.f/CC) + 1e-5f);
        #pragma unroll 4
        for(int k=0;k<64;k+=2){
            int c = cb + k;
            float y0 = (Crow[k]  -mean)*inv*lg[c]   + lb[c];
            float y1 = (Crow[k+1]-mean)*inv*lg[c+1] + lb[c+1];
            y0 = fmaxf(y0, 0.f); y1 = fmaxf(y1, 0.f);
            *(float2*)&xo[(size_t)n*CC + c] = make_float2(y0, y1);
            __nv_bfloat16 h0 = __float2bfloat16(y0), h1 = __float2bfloat16(y1);
            *(__nv_bfloat162*)&g_xh[(size_t)n*CC + c] = __nv_bfloat162(h0, h1);
            *(__nv_bfloat162*)&g_xl[(size_t)n*CC + c] = __nv_bfloat162(
                __float2bfloat16(y0 - __bfloat162float(h0)),
                __float2bfloat16(y1 - __bfloat162float(h1)));
        }
    }
}

// ---------------- output MLP on supernodes -----------------------------------
__global__ void mlp_kernel(int sel, const float* __restrict__ W, const float* __restrict__ b){
    const float* in  = sel ? g_m1 : g_x;
    float*       out = sel ? g_m2 : g_m1;
    __shared__ float row[CC];
    int g = blockIdx.x, c = threadIdx.x;
    row[c] = in[(size_t)g*CC + c];
    __syncthreads();
    float acc = b[c];
    const float* w = &W[(size_t)c*CC];
    #pragma unroll 8
    for(int k2=0;k2<CC;k2++) acc += row[k2]*w[k2];
    out[(size_t)g*CC + c] = fmaxf(acc, 0.f);
}

__global__ void final_kernel(const float* __restrict__ Wp, const float* __restrict__ bp,
                             float* __restrict__ out){
    int warp = (blockIdx.x*blockDim.x + threadIdx.x) >> 5;
    int lane = threadIdx.x & 31;
    if(warp >= GG) return;
    float a = 0.f;
    #pragma unroll
    for(int i=0;i<4;i++){
        int c = lane + 32*i;
        a += g_m2[(size_t)warp*CC + c] * Wp[c];
    }
    #pragma unroll
    for(int o=16;o>0;o>>=1) a += __shfl_xor_sync(0xffffffffu, a, o);
    if(lane==0) out[warp] = a + bp[0];
}

// ---------------- launch -----------------------------------------------------
extern "C" void kernel_launch(void* const* d_in, const int* in_sizes, int n_in,
                              void* d_out, int out_size)
{
    const int*   atoms = (const int*)d_in[0];
    const int*   ei    = (const int*)d_in[1];
    const int*   src   = ei;
    const int*   dstp  = ei + EE;
    const float* embd  = (const float*)d_in[2];
    const float* Wq    = (const float*)d_in[3];
    const float* bq    = (const float*)d_in[4];
    const float* Wk    = (const float*)d_in[5];
    const float* bk    = (const float*)d_in[6];  (void)bk; // softmax-invariant
    const float* Wv    = (const float*)d_in[7];
    const float* bv    = (const float*)d_in[8];
    const float* Ws    = (const float*)d_in[9];
    const float* bs    = (const float*)d_in[10];
    const float* lg    = (const float*)d_in[11];
    const float* lb    = (const float*)d_in[12];
    const float* Wlin  = (const float*)d_in[13];
    const float* blin  = (const float*)d_in[14];
    const float* Wp    = (const float*)d_in[15];
    const float* bp    = (const float*)d_in[16];
    float* out = (float*)d_out;

    cudaFuncSetAttribute(gemm_p, cudaFuncAttributeMaxDynamicSharedMemorySize, GP_SMEM);
    cudaFuncSetAttribute(gemm_b, cudaFuncAttributeMaxDynamicSharedMemorySize, GB_SMEM);

    // order chosen so my 4th launch is gemm_p(l=0) (ncu target)
    prep_kernel<<<10282, 128>>>(Wq, Wk, Wv, Ws, bq, bv);           // 1
    embed_kernel<<<NN*CC/256, 256>>>(atoms, embd);                 // 2
    hist_kernel<<<EE/256, 256>>>(dstp);                            // 3
    gemm_p<<<dim3(PC/128, NN/128), 256, GP_SMEM>>>(0);             // 4 <- ncu target
    scan_kernel<<<1, 1024>>>();                                    // 5
    scatter_kernel<<<EE/256, 256>>>(src, dstp);                    // 6
    attn_kernel<<<NN/8, 256>>>(0);                                 // 7
    gemm_b<<<NN/128, 256, GB_SMEM>>>(0, 0, bs, lg, lb);            // 8

    for(int l=1; l<LL; l++){
        int parity = l & 1;
        gemm_p<<<dim3(PC/128, NN/128), 256, GP_SMEM>>>(l);
        attn_kernel<<<NN/8, 256>>>(parity);
        gemm_b<<<NN/128, 256, GB_SMEM>>>(l, parity, bs + (size_t)l*CC,
                                         lg + (size_t)l*CC, lb + (size_t)l*CC);
    }

    mlp_kernel<<<GG, CC>>>(0, Wlin,         blin);
    mlp_kernel<<<GG, CC>>>(1, Wlin + CC*CC, blin + CC);
    final_kernel<<<GG*32/256, 256>>>(Wp, bp, out);
}

// round 9
// speedup vs baseline: 1.1669x; 1.1669x over previous
#include <cuda_runtime.h>
#include <cuda_bf16.h>
#include <math.h>

#define NN 32768
#define EE 131072
#define HH 6
#define CC 128
#define LL 6
#define GG 2048
#define PC 768      // p / y width (H*C)
#define KB 896      // gemm B K dim (768 y + 128 x)

// ---------------- scratch (device globals) -----------------------------------
__device__ float g_x[NN*CC];
__device__ float g_xn[NN*CC];
__device__ __nv_bfloat16 g_xh[NN*CC];
__device__ __nv_bfloat16 g_xl[NN*CC];
__device__ __nv_bfloat16 g_pb[NN*PC];       // p, bf16, 1/sqrt(C) folded
__device__ __nv_bfloat16 g_yh[NN*PC];
__device__ __nv_bfloat16 g_yl[NN*PC];
__device__ __nv_bfloat16 g_WAh[LL*PC*CC];   // Wqk = Wk^T Wq per head, bf16
__device__ float g_bqk[LL*PC];
__device__ __nv_bfloat16 g_WBh[LL*CC*KB];   // [Wv/H | Ws^T] combined, bf16 hi
__device__ __nv_bfloat16 g_WBl[LL*CC*KB];
__device__ float g_bvm[LL*CC];              // mean_h bv
__device__ int   g_deg[NN];
__device__ int   g_cnt[NN];
__device__ int   g_off[NN+1];
__device__ int   g_srcs[EE];                // CSR-ordered source node ids
__device__ float g_m1[GG*CC];
__device__ float g_m2[GG*CC];

// ---------------- prep: fold weights + zero counters (single launch) ---------
__global__ void prep_kernel(
    const float* __restrict__ Wq, const float* __restrict__ Wk,
    const float* __restrict__ Wv, const float* __restrict__ Ws,
    const float* __restrict__ bq, const float* __restrict__ bv)
{
    int bid = blockIdx.x, tid = threadIdx.x;
    if(bid < 4608){
        // Wqk_h[c,c2] = sum_cc Wk[h*128+cc, c] * Wq[h*128+cc, c2]
        int l = bid / (HH*CC);
        int rem = bid % (HH*CC);
        int h = rem >> 7, c = rem & 127;
        __shared__ float wk[128];
        wk[tid] = Wk[((size_t)l*PC + h*CC + tid)*CC + c];
        __syncthreads();
        float acc = 0.f;
        const float* wqp = &Wq[((size_t)l*PC + h*CC)*CC + tid];
        #pragma unroll 8
        for(int cc=0; cc<CC; cc++) acc += wk[cc] * wqp[(size_t)cc*CC];
        g_WAh[((size_t)l*PC + h*CC + c)*CC + tid] = __float2bfloat16(acc);
    } else if(bid < 4644){
        int b2 = bid - 4608;
        int l = b2 / HH, h = b2 % HH;
        float acc = 0.f;
        for(int cc=0; cc<CC; cc++)
            acc += bq[l*PC + h*CC + cc] * Wk[((size_t)l*PC + h*CC + cc)*CC + tid];
        g_bqk[l*PC + h*CC + tid] = acc;
    } else if(bid < 10020){
        int idx = (bid-4644)*128 + tid;          // over LL*CC*KB
        int l = idx / (CC*KB);
        int j = (idx / KB) % CC;
        int c = idx % KB;
        float v;
        if(c < PC){
            int h = c >> 7, cp = c & 127;
            v = Wv[((size_t)l*PC + h*CC + j)*CC + cp] * (1.f/HH);
        } else {
            v = Ws[((size_t)l*CC + j)*CC + (c - PC)];
        }
        size_t o = ((size_t)l*CC + j)*KB + c;
        __nv_bfloat16 hi = __float2bfloat16(v);
        g_WBh[o] = hi;
        g_WBl[o] = __float2bfloat16(v - __bfloat162float(hi));
    } else if(bid < 10276){
        int i = (bid-10020)*128 + tid;
        g_deg[i]=0; g_cnt[i]=0;
    } else {
        int i = (bid-10276)*128 + tid;           // LL*CC
        int l = i >> 7, j = i & 127;
        float a = 0.f;
        #pragma unroll
        for(int h=0;h<HH;h++) a += bv[l*PC + h*CC + j];
        g_bvm[i] = a * (1.f/HH);
    }
}

// ---------------- CSR build --------------------------------------------------
__global__ void hist_kernel(const int* __restrict__ dst){
    int e = blockIdx.x*blockDim.x + threadIdx.x;
    if(e < EE) atomicAdd(&g_deg[dst[e]], 1);
}
__global__ void scan_kernel(){
    __shared__ int sh[1024];
    __shared__ int sbase;
    int tid = threadIdx.x;
    if(tid==0){ sbase = 0; g_off[0] = 0; }
    __syncthreads();
    for(int chunk=0; chunk<NN/1024; chunk++){
        int idx = chunk*1024 + tid;
        sh[tid] = g_deg[idx];
        __syncthreads();
        for(int o=1;o<1024;o<<=1){
            int t = (tid>=o) ? sh[tid-o] : 0;
            __syncthreads();
            sh[tid] += t;
            __syncthreads();
        }
        g_off[idx+1] = sbase + sh[tid];
        __syncthreads();
        if(tid==1023) sbase += sh[1023];
        __syncthreads();
    }
}
__global__ void scatter_kernel(const int* __restrict__ src, const int* __restrict__ dst){
    int e = blockIdx.x*blockDim.x + threadIdx.x;
    if(e < EE){
        int d = dst[e];
        int pos = g_off[d] + atomicAdd(&g_cnt[d], 1);
        g_srcs[pos] = src[e];
    }
}

// ---------------- embedding (+ bf16 split) -----------------------------------
__global__ void embed_kernel(const int* __restrict__ atoms, const float* __restrict__ embd){
    int i = blockIdx.x*blockDim.x + threadIdx.x;
    int n = i >> 7, c = i & 127;
    float v = embd[atoms[n]*CC + c];
    g_x[i] = v;
    __nv_bfloat16 h = __float2bfloat16(v);
    g_xh[i] = h;
    g_xl[i] = __float2bfloat16(v - __bfloat162float(h));
}

// ---------------- MMA / LDSM / cp.async macros --------------------------------
#define MMA16816(d, a, b) asm volatile( \
    "mma.sync.aligned.m16n8k16.row.col.f32.bf16.bf16.f32 " \
    "{%0,%1,%2,%3}, {%4,%5,%6,%7}, {%8,%9}, {%0,%1,%2,%3};" \
    : "+f"(d[0]),"+f"(d[1]),"+f"(d[2]),"+f"(d[3]) \
    : "r"(a[0]),"r"(a[1]),"r"(a[2]),"r"(a[3]), "r"(b[0]),"r"(b[1]))

#define LDSM_X4(R0,R1,R2,R3,A) asm volatile( \
    "ldmatrix.sync.aligned.m8n8.x4.shared.b16 {%0,%1,%2,%3}, [%4];" \
    : "=r"(R0),"=r"(R1),"=r"(R2),"=r"(R3) : "r"(A))

#define CPASYNC16(saddr, gptr) asm volatile( \
    "cp.async.cg.shared.global [%0], [%1], 16;" :: "r"(saddr), "l"(gptr))
#define CPCOMMIT() asm volatile("cp.async.commit_group;" ::: "memory")
#define CPWAIT(n)  asm volatile("cp.async.wait_group %0;" :: "n"(n) : "memory")

__device__ __forceinline__ unsigned smem_u32p(const void* p){
    return (unsigned)__cvta_generic_to_shared(p);
}

// ---------------- GEMM A: p = (x @ Wqk^T + bqk)/sqrt(C), 128x128 tiles -------
// (R7 version — measured best)
__global__ __launch_bounds__(256) void gemm_p(int layer)
{
    __shared__ __nv_bfloat16 sA[128][72], sB[128][72];
    int col0 = blockIdx.x * 128;
    int row0 = blockIdx.y * 128;
    int tid = threadIdx.x, warp = tid >> 5, lane = tid & 31;
    int wm = warp >> 2, wn = warp & 3;      // 2 x 4 warp grid
    int wr0 = wm * 64, wc0 = wn * 32;       // warp tile 64 x 32
    int gid = lane >> 2, tig = lane & 3;

    float acc[4][4][4];
    #pragma unroll
    for(int i=0;i<4;i++)
        #pragma unroll
        for(int j=0;j<4;j++)
            #pragma unroll
            for(int t=0;t<4;t++) acc[i][j][t] = 0.f;

    int lr = tid >> 1;              // 0..127
    int lc = (tid & 1) * 32;        // 0 or 32 (each thread: 32 bf16 = 4 uint4)
    const __nv_bfloat16* Ag = &g_xh[(size_t)(row0+lr)*CC + lc];
    const __nv_bfloat16* Bg = &g_WAh[((size_t)layer*PC + col0 + lr)*CC + lc];

    unsigned aAddr[4], bAddr[2];
    #pragma unroll
    for(int i=0;i<4;i++)
        aAddr[i] = smem_u32p(&sA[wr0 + i*16 + (lane & 15)][(lane >> 4) * 8]);
    #pragma unroll
    for(int g=0; g<2; g++)
        bAddr[g] = smem_u32p(&sB[wc0 + g*16 + (lane & 7) + ((lane >> 4) << 3)][((lane >> 3) & 1) * 8]);

    #pragma unroll
    for(int kit=0; kit<2; kit++){
        int k0 = kit * 64;
        #pragma unroll
        for(int q=0;q<4;q++){
            *(uint4*)&sA[lr][lc + 8*q] = *(const uint4*)(Ag + k0 + 8*q);
            *(uint4*)&sB[lr][lc + 8*q] = *(const uint4*)(Bg + k0 + 8*q);
        }
        __syncthreads();
        #pragma unroll
        for(int ks=0; ks<64; ks+=16){
            unsigned a_[4][4], b_[4][2];
            #pragma unroll
            for(int i=0;i<4;i++)
                LDSM_X4(a_[i][0], a_[i][1], a_[i][2], a_[i][3], aAddr[i] + ks*2);
            #pragma unroll
            for(int g=0; g<2; g++)
                LDSM_X4(b_[g*2][0], b_[g*2][1], b_[g*2+1][0], b_[g*2+1][1], bAddr[g] + ks*2);
            #pragma unroll
            for(int i=0;i<4;i++)
                #pragma unroll
                for(int j=0;j<4;j++)
                    MMA16816(acc[i][j], a_[i], b_[j]);
        }
        __syncthreads();
    }

    const float invsq = 0.08838834764831845f;  // 1/sqrt(128)
    #pragma unroll
    for(int i=0;i<4;i++){
        int r = row0 + wr0 + i*16 + gid;
        #pragma unroll
        for(int j=0;j<4;j++){
            int c = col0 + wc0 + j*8 + 2*tig;
            float b0 = g_bqk[layer*PC + c], b1 = g_bqk[layer*PC + c + 1];
            *(__nv_bfloat162*)&g_pb[(size_t)r*PC + c] = __nv_bfloat162(
                __float2bfloat16((acc[i][j][0] + b0)*invsq),
                __float2bfloat16((acc[i][j][1] + b1)*invsq));
            *(__nv_bfloat162*)&g_pb[(size_t)(r+8)*PC + c] = __nv_bfloat162(
                __float2bfloat16((acc[i][j][2] + b0)*invsq),
                __float2bfloat16((acc[i][j][3] + b1)*invsq));
        }
    }
}

// ---------------- attention: plain-sum softmax (scores provably small) -------
__global__ __launch_bounds__(256) void attn_kernel(int parity)
{
    const float4* x4 = (const float4*)(parity ? g_xn : g_x);
    int warp = (blockIdx.x*blockDim.x + threadIdx.x) >> 5;
    int lane = threadIdx.x & 31;
    if(warp >= NN) return;
    int d = warp;

    const __nv_bfloat162* pb = (const __nv_bfloat162*)&g_pb[(size_t)d*PC];
    float4 p[HH];
    #pragma unroll
    for(int h=0;h<HH;h++){
        float2 f0 = __bfloat1622float2(pb[h*64 + lane*2]);
        float2 f1 = __bfloat1622float2(pb[h*64 + lane*2 + 1]);
        p[h] = make_float4(f0.x, f0.y, f1.x, f1.y);
    }

    int e0 = g_off[d], e1 = g_off[d+1];
    float den[HH];
    float4 y[HH];
    #pragma unroll
    for(int h=0;h<HH;h++){ den[h]=0.f; y[h]=make_float4(0.f,0.f,0.f,0.f); }

    for(int t=e0; t<e1; t++){
        int s = g_srcs[t];
        float4 xv = x4[(size_t)s*32 + lane];
        float dot[HH];
        #pragma unroll
        for(int h=0;h<HH;h++)
            dot[h] = p[h].x*xv.x + p[h].y*xv.y + p[h].z*xv.z + p[h].w*xv.w;
        #pragma unroll
        for(int h=0;h<HH;h++){
            #pragma unroll
            for(int o=16;o>0;o>>=1) dot[h] += __shfl_xor_sync(0xffffffffu, dot[h], o);
        }
        #pragma unroll
        for(int h=0;h<HH;h++){
            float ex = __expf(fminf(dot[h], 80.f));   // softmax shift-invariant; clamp = overflow guard
            den[h] += ex;
            y[h].x += ex*xv.x;
            y[h].y += ex*xv.y;
            y[h].z += ex*xv.z;
            y[h].w += ex*xv.w;
        }
    }

    size_t base = (size_t)d*PC;
    #pragma unroll
    for(int h=0;h<HH;h++){
        float r = (den[h] > 0.f) ? 1.f/den[h] : 0.f;
        float v0=y[h].x*r, v1=y[h].y*r, v2=y[h].z*r, v3=y[h].w*r;
        int c = h*CC + lane*4;
        __nv_bfloat16 h0=__float2bfloat16(v0), h1=__float2bfloat16(v1);
        __nv_bfloat16 h2=__float2bfloat16(v2), h3=__float2bfloat16(v3);
        *(__nv_bfloat162*)&g_yh[base+c]   = __nv_bfloat162(h0, h1);
        *(__nv_bfloat162*)&g_yh[base+c+2] = __nv_bfloat162(h2, h3);
        __nv_bfloat16 l0=__float2bfloat16(v0-__bfloat162float(h0));
        __nv_bfloat16 l1=__float2bfloat16(v1-__bfloat162float(h1));
        __nv_bfloat16 l2=__float2bfloat16(v2-__bfloat162float(h2));
        __nv_bfloat16 l3=__float2bfloat16(v3-__bfloat162float(h3));
        *(__nv_bfloat162*)&g_yl[base+c]   = __nv_bfloat162(l0, l1);
        *(__nv_bfloat162*)&g_yl[base+c+2] = __nv_bfloat162(l2, l3);
    }
}

// ---------------- GEMM B: out = [y|x] @ WB^T (+bias,+res) -> LN -> ReLU ------
// 128x128 tile, K=896 in 28 chunks of 32; 3-pass hi/lo; double-buffered
// cp.async pipeline at 2 CTAs/SM. smem: 2 stages x (Ah|Al|Bh|Bl each 128x40
// bf16 = 10240 B) = 81920 B; epilogue C fp32 [128][132] (67584 B) reuses it.
#define GB_SEG 10240
#define GB_STAGE (4*GB_SEG)          // 40960
#define GB_SMEM (2*GB_STAGE)         // 81920
__global__ __launch_bounds__(256,2) void gemm_b(
    int layer, int parity,
    const float* __restrict__ bs, const float* __restrict__ lg, const float* __restrict__ lb)
{
    extern __shared__ char dsm[];
    __nv_bfloat16 (*Ah)[40] = (__nv_bfloat16(*)[40])(dsm);
    __nv_bfloat16 (*Al)[40] = (__nv_bfloat16(*)[40])(dsm + GB_SEG);
    __nv_bfloat16 (*Bh)[40] = (__nv_bfloat16(*)[40])(dsm + 2*GB_SEG);
    __nv_bfloat16 (*Bl)[40] = (__nv_bfloat16(*)[40])(dsm + 3*GB_SEG);

    const float* xold = parity ? g_xn : g_x;
    float*       xo   = parity ? g_x  : g_xn;
    int row0 = blockIdx.x * 128;
    int tid = threadIdx.x, warp = tid >> 5, lane = tid & 31;
    int wm = warp >> 2, wn = warp & 3;
    int wr0 = wm * 64, wc0 = wn * 32;
    int gid = lane >> 2, tig = lane & 3;

    float acc[4][4][4];
    #pragma unroll
    for(int i=0;i<4;i++)
        #pragma unroll
        for(int j=0;j<4;j++)
            #pragma unroll
            for(int t=0;t<4;t++) acc[i][j][t] = 0.f;

    int lr = tid >> 1;              // row 0..127
    int lc = (tid & 1) * 16;        // cols 0-15 or 16-31 (2 x 16B per thread)
    unsigned stAh = smem_u32p(&Ah[lr][lc]);
    unsigned stAl = smem_u32p(&Al[lr][lc]);
    unsigned stBh = smem_u32p(&Bh[lr][lc]);
    unsigned stBl = smem_u32p(&Bl[lr][lc]);

    unsigned aAddrH[4], aAddrL[4], bAddrH[2], bAddrL[2];
    {
        int arow = lane & 15, ak = (lane >> 4) * 8;
        #pragma unroll
        for(int i=0;i<4;i++){
            aAddrH[i] = smem_u32p(&Ah[wr0 + i*16 + arow][ak]);
            aAddrL[i] = smem_u32p(&Al[wr0 + i*16 + arow][ak]);
        }
        int bcol = (lane & 7) + ((lane >> 4) << 3);
        int bk = ((lane >> 3) & 1) * 8;
        #pragma unroll
        for(int g=0; g<2; g++){
            bAddrH[g] = smem_u32p(&Bh[wc0 + g*16 + bcol][bk]);
            bAddrL[g] = smem_u32p(&Bl[wc0 + g*16 + bcol][bk]);
        }
    }

    // one stage: 8 cp.async of 16B per thread
    auto issue = [&](int s){
        int k0 = s * 32;
        unsigned so = (unsigned)(s & 1) * GB_STAGE;
        const __nv_bfloat16 *ah, *al;
        if(k0 < PC){
            ah = &g_yh[(size_t)(row0+lr)*PC + k0 + lc];
            al = &g_yl[(size_t)(row0+lr)*PC + k0 + lc];
        } else {
            ah = &g_xh[(size_t)(row0+lr)*CC + (k0 - PC) + lc];
            al = &g_xl[(size_t)(row0+lr)*CC + (k0 - PC) + lc];
        }
        const __nv_bfloat16* bhg = &g_WBh[((size_t)layer*CC + lr)*KB + k0 + lc];
        const __nv_bfloat16* blg = &g_WBl[((size_t)layer*CC + lr)*KB + k0 + lc];
        CPASYNC16(stAh + so,      ah);
        CPASYNC16(stAh + so + 16, ah + 8);
        CPASYNC16(stAl + so,      al);
        CPASYNC16(stAl + so + 16, al + 8);
        CPASYNC16(stBh + so,      bhg);
        CPASYNC16(stBh + so + 16, bhg + 8);
        CPASYNC16(stBl + so,      blg);
        CPASYNC16(stBl + so + 16, blg + 8);
        CPCOMMIT();
    };

    issue(0);
    for(int s=0; s<28; s++){
        if(s < 27){ issue(s+1); CPWAIT(1); }
        else      { CPWAIT(0); }
        __syncthreads();
        unsigned bo = (unsigned)(s & 1) * GB_STAGE;

        #pragma unroll
        for(int ks=0; ks<32; ks+=16){
            unsigned bh_[4][2], bl_[4][2], a_[4][4];
            #pragma unroll
            for(int g=0; g<2; g++){
                LDSM_X4(bh_[g*2][0], bh_[g*2][1], bh_[g*2+1][0], bh_[g*2+1][1], bAddrH[g] + bo + ks*2);
                LDSM_X4(bl_[g*2][0], bl_[g*2][1], bl_[g*2+1][0], bl_[g*2+1][1], bAddrL[g] + bo + ks*2);
            }
            #pragma unroll
            for(int i=0;i<4;i++)
                LDSM_X4(a_[i][0], a_[i][1], a_[i][2], a_[i][3], aAddrH[i] + bo + ks*2);
            #pragma unroll
            for(int i=0;i<4;i++)
                #pragma unroll
                for(int j=0;j<4;j++){
                    MMA16816(acc[i][j], a_[i], bh_[j]);
                    MMA16816(acc[i][j], a_[i], bl_[j]);
                }
            #pragma unroll
            for(int i=0;i<4;i++)
                LDSM_X4(a_[i][0], a_[i][1], a_[i][2], a_[i][3], aAddrL[i] + bo + ks*2);
            #pragma unroll
            for(int i=0;i<4;i++)
                #pragma unroll
                for(int j=0;j<4;j++)
                    MMA16816(acc[i][j], a_[i], bh_[j]);
        }
        __syncthreads();
    }

    // dump accumulators to smem C (stride 132 floats)
    float* Csm = (float*)dsm;
    #pragma unroll
    for(int i=0;i<4;i++){
        int r = wr0 + i*16 + gid;
        #pragma unroll
        for(int j=0;j<4;j++){
            int c = wc0 + j*8 + 2*tig;
            Csm[r*132 + c]       = acc[i][j][0];
            Csm[r*132 + c + 1]   = acc[i][j][1];
            Csm[(r+8)*132 + c]   = acc[i][j][2];
            Csm[(r+8)*132 + c+1] = acc[i][j][3];
        }
    }
    __syncthreads();

    // epilogue: 2 threads per row, 64 channels each
    {
        int row = tid >> 1, half = tid & 1;
        int n = row0 + row;
        float* Crow = Csm + row*132 + half*64;
        float flag = (g_off[n+1] > g_off[n]) ? 1.f : 0.f;
        const float* xr = &xold[(size_t)n*CC + half*64];
        int cb = half*64;
        float s1 = 0.f;
        #pragma unroll 8
        for(int k=0;k<64;k++){
            int c = cb + k;
            float v = Crow[k] + bs[c] + flag*g_bvm[layer*CC + c] + xr[k];
            Crow[k] = v;
            s1 += v;
        }
        s1 += __shfl_xor_sync(0xffffffffu, s1, 1);
        float mean = s1 * (1.f/CC);
        float s2 = 0.f;
        #pragma unroll 8
        for(int k=0;k<64;k++){ float dv = Crow[k]-mean; s2 += dv*dv; }
        s2 += __shfl_xor_sync(0xffffffffu, s2, 1);
        float inv = rsqrtf(s2*(1.f/CC) + 1e-5f);
        #pragma unroll 4
        for(int k=0;k<64;k+=2){
            int c = cb + k;
            float y0 = (Crow[k]  -mean)*inv*lg[c]   + lb[c];
            float y1 = (Crow[k+1]-mean)*inv*lg[c+1] + lb[c+1];
            y0 = fmaxf(y0, 0.f); y1 = fmaxf(y1, 0.f);
            *(float2*)&xo[(size_t)n*CC + c] = make_float2(y0, y1);
            __nv_bfloat16 h0 = __float2bfloat16(y0), h1 = __float2bfloat16(y1);
            *(__nv_bfloat162*)&g_xh[(size_t)n*CC + c] = __nv_bfloat162(h0, h1);
            *(__nv_bfloat162*)&g_xl[(size_t)n*CC + c] = __nv_bfloat162(
                __float2bfloat16(y0 - __bfloat162float(h0)),
                __float2bfloat16(y1 - __bfloat162float(h1)));
        }
    }
}

// ---------------- output MLP on supernodes -----------------------------------
__global__ void mlp_kernel(int sel, const float* __restrict__ W, const float* __restrict__ b){
    const float* in  = sel ? g_m1 : g_x;
    float*       out = sel ? g_m2 : g_m1;
    __shared__ float row[CC];
    int g = blockIdx.x, c = threadIdx.x;
    row[c] = in[(size_t)g*CC + c];
    __syncthreads();
    float acc = b[c];
    const float* w = &W[(size_t)c*CC];
    #pragma unroll 8
    for(int k2=0;k2<CC;k2++) acc += row[k2]*w[k2];
    out[(size_t)g*CC + c] = fmaxf(acc, 0.f);
}

__global__ void final_kernel(const float* __restrict__ Wp, const float* __restrict__ bp,
                             float* __restrict__ out){
    int warp = (blockIdx.x*blockDim.x + threadIdx.x) >> 5;
    int lane = threadIdx.x & 31;
    if(warp >= GG) return;
    float a = 0.f;
    #pragma unroll
    for(int i=0;i<4;i++){
        int c = lane + 32*i;
        a += g_m2[(size_t)warp*CC + c] * Wp[c];
    }
    #pragma unroll
    for(int o=16;o>0;o>>=1) a += __shfl_xor_sync(0xffffffffu, a, o);
    if(lane==0) out[warp] = a + bp[0];
}

// ---------------- launch -----------------------------------------------------
extern "C" void kernel_launch(void* const* d_in, const int* in_sizes, int n_in,
                              void* d_out, int out_size)
{
    const int*   atoms = (const int*)d_in[0];
    const int*   ei    = (const int*)d_in[1];
    const int*   src   = ei;
    const int*   dstp  = ei + EE;
    const float* embd  = (const float*)d_in[2];
    const float* Wq    = (const float*)d_in[3];
    const float* bq    = (const float*)d_in[4];
    const float* Wk    = (const float*)d_in[5];
    const float* bk    = (const float*)d_in[6];  (void)bk; // softmax-invariant
    const float* Wv    = (const float*)d_in[7];
    const float* bv    = (const float*)d_in[8];
    const float* Ws    = (const float*)d_in[9];
    const float* bs    = (const float*)d_in[10];
    const float* lg    = (const float*)d_in[11];
    const float* lb    = (const float*)d_in[12];
    const float* Wlin  = (const float*)d_in[13];
    const float* blin  = (const float*)d_in[14];
    const float* Wp    = (const float*)d_in[15];
    const float* bp    = (const float*)d_in[16];
    float* out = (float*)d_out;

    cudaFuncSetAttribute(gemm_b, cudaFuncAttributeMaxDynamicSharedMemorySize, GB_SMEM);

    // order chosen so my 4th launch is gemm_p(l=0) (ncu target)
    prep_kernel<<<10282, 128>>>(Wq, Wk, Wv, Ws, bq, bv);           // 1
    embed_kernel<<<NN*CC/256, 256>>>(atoms, embd);                 // 2
    hist_kernel<<<EE/256, 256>>>(dstp);                            // 3
    gemm_p<<<dim3(PC/128, NN/128), 256>>>(0);                      // 4 <- ncu target
    scan_kernel<<<1, 1024>>>();                                    // 5
    scatter_kernel<<<EE/256, 256>>>(src, dstp);                    // 6
    attn_kernel<<<NN/8, 256>>>(0);                                 // 7
    gemm_b<<<NN/128, 256, GB_SMEM>>>(0, 0, bs, lg, lb);            // 8

    for(int l=1; l<LL; l++){
        int parity = l & 1;
        gemm_p<<<dim3(PC/128, NN/128), 256>>>(l);
        attn_kernel<<<NN/8, 256>>>(parity);
        gemm_b<<<NN/128, 256, GB_SMEM>>>(l, parity, bs + (size_t)l*CC,
                                         lg + (size_t)l*CC, lb + (size_t)l*CC);
    }

    mlp_kernel<<<GG, CC>>>(0, Wlin,         blin);
    mlp_kernel<<<GG, CC>>>(1, Wlin + CC*CC, blin + CC);
    final_kernel<<<GG*32/256, 256>>>(Wp, bp, out);
}

// round 11
// speedup vs baseline: 1.1862x; 1.0165x over previous
#include <cuda_runtime.h>
#include <cuda_bf16.h>
#include <math.h>

#define NN 32768
#define EE 131072
#define HH 6
#define CC 128
#define LL 6
#define GG 2048
#define PC 768      // p / y width (H*C)
#define KB 896      // gemm B K dim (768 y + 128 x)

// ---------------- scratch (device globals) -----------------------------------
__device__ float g_x[NN*CC];
__device__ float g_xn[NN*CC];
__device__ __nv_bfloat16 g_xh[NN*CC];
__device__ __nv_bfloat16 g_xl[NN*CC];
__device__ __nv_bfloat16 g_pb[NN*PC];       // p, bf16, 1/sqrt(C) folded
__device__ __nv_bfloat16 g_yh[NN*PC];
__device__ __nv_bfloat16 g_yl[NN*PC];
__device__ __nv_bfloat16 g_WAh[LL*PC*CC];   // Wqk = Wk^T Wq per head, bf16
__device__ float g_bqk[LL*PC];
__device__ __nv_bfloat16 g_WBh[LL*CC*KB];   // [Wv/H | Ws^T] combined, bf16 hi
__device__ __nv_bfloat16 g_WBl[LL*CC*KB];
__device__ float g_bvm[LL*CC];              // mean_h bv
__device__ int   g_deg[NN];
__device__ int   g_cnt[NN];
__device__ int   g_off[NN+1];
__device__ int   g_srcs[EE];                // CSR-ordered source node ids
__device__ float g_m1[GG*CC];
__device__ float g_m2[GG*CC];

// ---------------- prep: fold weights + zero counters (single launch) ---------
__global__ void prep_kernel(
    const float* __restrict__ Wq, const float* __restrict__ Wk,
    const float* __restrict__ Wv, const float* __restrict__ Ws,
    const float* __restrict__ bq, const float* __restrict__ bv)
{
    int bid = blockIdx.x, tid = threadIdx.x;
    if(bid < 4608){
        // Wqk_h[c,c2] = sum_cc Wk[h*128+cc, c] * Wq[h*128+cc, c2]
        int l = bid / (HH*CC);
        int rem = bid % (HH*CC);
        int h = rem >> 7, c = rem & 127;
        __shared__ float wk[128];
        wk[tid] = Wk[((size_t)l*PC + h*CC + tid)*CC + c];
        __syncthreads();
        float acc = 0.f;
        const float* wqp = &Wq[((size_t)l*PC + h*CC)*CC + tid];
        #pragma unroll 8
        for(int cc=0; cc<CC; cc++) acc += wk[cc] * wqp[(size_t)cc*CC];
        g_WAh[((size_t)l*PC + h*CC + c)*CC + tid] = __float2bfloat16(acc);
    } else if(bid < 4644){
        int b2 = bid - 4608;
        int l = b2 / HH, h = b2 % HH;
        float acc = 0.f;
        for(int cc=0; cc<CC; cc++)
            acc += bq[l*PC + h*CC + cc] * Wk[((size_t)l*PC + h*CC + cc)*CC + tid];
        g_bqk[l*PC + h*CC + tid] = acc;
    } else if(bid < 10020){
        int idx = (bid-4644)*128 + tid;          // over LL*CC*KB
        int l = idx / (CC*KB);
        int j = (idx / KB) % CC;
        int c = idx % KB;
        float v;
        if(c < PC){
            int h = c >> 7, cp = c & 127;
            v = Wv[((size_t)l*PC + h*CC + j)*CC + cp] * (1.f/HH);
        } else {
            v = Ws[((size_t)l*CC + j)*CC + (c - PC)];
        }
        size_t o = ((size_t)l*CC + j)*KB + c;
        __nv_bfloat16 hi = __float2bfloat16(v);
        g_WBh[o] = hi;
        g_WBl[o] = __float2bfloat16(v - __bfloat162float(hi));
    } else if(bid < 10276){
        int i = (bid-10020)*128 + tid;
        g_deg[i]=0; g_cnt[i]=0;
    } else {
        int i = (bid-10276)*128 + tid;           // LL*CC
        int l = i >> 7, j = i & 127;
        float a = 0.f;
        #pragma unroll
        for(int h=0;h<HH;h++) a += bv[l*PC + h*CC + j];
        g_bvm[i] = a * (1.f/HH);
    }
}

// ---------------- CSR build --------------------------------------------------
__global__ void hist_kernel(const int* __restrict__ dst){
    int e = blockIdx.x*blockDim.x + threadIdx.x;
    if(e < EE) atomicAdd(&g_deg[dst[e]], 1);
}
__global__ void scan_kernel(){
    __shared__ int sh[1024];
    __shared__ int sbase;
    int tid = threadIdx.x;
    if(tid==0){ sbase = 0; g_off[0] = 0; }
    __syncthreads();
    for(int chunk=0; chunk<NN/1024; chunk++){
        int idx = chunk*1024 + tid;
        sh[tid] = g_deg[idx];
        __syncthreads();
        for(int o=1;o<1024;o<<=1){
            int t = (tid>=o) ? sh[tid-o] : 0;
            __syncthreads();
            sh[tid] += t;
            __syncthreads();
        }
        g_off[idx+1] = sbase + sh[tid];
        __syncthreads();
        if(tid==1023) sbase += sh[1023];
        __syncthreads();
    }
}
__global__ void scatter_kernel(const int* __restrict__ src, const int* __restrict__ dst){
    int e = blockIdx.x*blockDim.x + threadIdx.x;
    if(e < EE){
        int d = dst[e];
        int pos = g_off[d] + atomicAdd(&g_cnt[d], 1);
        g_srcs[pos] = src[e];
    }
}

// ---------------- embedding (+ bf16 split) -----------------------------------
__global__ void embed_kernel(const int* __restrict__ atoms, const float* __restrict__ embd){
    int i = blockIdx.x*blockDim.x + threadIdx.x;
    int n = i >> 7, c = i & 127;
    float v = embd[atoms[n]*CC + c];
    g_x[i] = v;
    __nv_bfloat16 h = __float2bfloat16(v);
    g_xh[i] = h;
    g_xl[i] = __float2bfloat16(v - __bfloat162float(h));
}

// ---------------- MMA / LDSM / cp.async macros --------------------------------
#define MMA16816(d, a, b) asm volatile( \
    "mma.sync.aligned.m16n8k16.row.col.f32.bf16.bf16.f32 " \
    "{%0,%1,%2,%3}, {%4,%5,%6,%7}, {%8,%9}, {%0,%1,%2,%3};" \
    : "+f"(d[0]),"+f"(d[1]),"+f"(d[2]),"+f"(d[3]) \
    : "r"(a[0]),"r"(a[1]),"r"(a[2]),"r"(a[3]), "r"(b[0]),"r"(b[1]))

#define LDSM_X4(R0,R1,R2,R3,A) asm volatile( \
    "ldmatrix.sync.aligned.m8n8.x4.shared.b16 {%0,%1,%2,%3}, [%4];" \
    : "=r"(R0),"=r"(R1),"=r"(R2),"=r"(R3) : "r"(A))

#define CPASYNC16(saddr, gptr) asm volatile( \
    "cp.async.cg.shared.global [%0], [%1], 16;" :: "r"(saddr), "l"(gptr))
#define CPCOMMIT() asm volatile("cp.async.commit_group;" ::: "memory")
#define CPWAIT(n)  asm volatile("cp.async.wait_group %0;" :: "n"(n) : "memory")

__device__ __forceinline__ unsigned smem_u32p(const void* p){
    return (unsigned)__cvta_generic_to_shared(p);
}

// ---------------- GEMM A: p = (x @ Wqk^T + bqk)/sqrt(C) ----------------------
// 128x128 CTA tile, 512 threads (16 warps 4x4, warp tile 32x32) for 32 warps/SM.
__global__ __launch_bounds__(512,2) void gemm_p(int layer)
{
    __shared__ __nv_bfloat16 sA[128][72], sB[128][72];
    int col0 = blockIdx.x * 128;
    int row0 = blockIdx.y * 128;
    int tid = threadIdx.x, warp = tid >> 5, lane = tid & 31;
    int wm = warp >> 2, wn = warp & 3;      // 4 x 4 warp grid
    int wr0 = wm * 32, wc0 = wn * 32;       // warp tile 32 x 32
    int gid = lane >> 2, tig = lane & 3;

    float acc[2][4][4];
    #pragma unroll
    for(int i=0;i<2;i++)
        #pragma unroll
        for(int j=0;j<4;j++)
            #pragma unroll
            for(int t=0;t<4;t++) acc[i][j][t] = 0.f;

    int lr = tid >> 2;              // 0..127
    int lc = (tid & 3) * 16;        // 16 bf16 = 2 uint4 per thread per chunk
    const __nv_bfloat16* Ag = &g_xh[(size_t)(row0+lr)*CC + lc];
    const __nv_bfloat16* Bg = &g_WAh[((size_t)layer*PC + col0 + lr)*CC + lc];

    unsigned aAddr[2], bAddr[2];
    #pragma unroll
    for(int i=0;i<2;i++)
        aAddr[i] = smem_u32p(&sA[wr0 + i*16 + (lane & 15)][(lane >> 4) * 8]);
    #pragma unroll
    for(int g=0; g<2; g++)
        bAddr[g] = smem_u32p(&sB[wc0 + g*16 + (lane & 7) + ((lane >> 4) << 3)][((lane >> 3) & 1) * 8]);

    #pragma unroll
    for(int kit=0; kit<2; kit++){
        int k0 = kit * 64;
        #pragma unroll
        for(int q=0;q<2;q++){
            *(uint4*)&sA[lr][lc + 8*q] = *(const uint4*)(Ag + k0 + 8*q);
            *(uint4*)&sB[lr][lc + 8*q] = *(const uint4*)(Bg + k0 + 8*q);
        }
        __syncthreads();
        #pragma unroll
        for(int ks=0; ks<64; ks+=16){
            unsigned a_[2][4], b_[4][2];
            #pragma unroll
            for(int i=0;i<2;i++)
                LDSM_X4(a_[i][0], a_[i][1], a_[i][2], a_[i][3], aAddr[i] + ks*2);
            #pragma unroll
            for(int g=0; g<2; g++)
                LDSM_X4(b_[g*2][0], b_[g*2][1], b_[g*2+1][0], b_[g*2+1][1], bAddr[g] + ks*2);
            #pragma unroll
            for(int i=0;i<2;i++)
                #pragma unroll
                for(int j=0;j<4;j++)
                    MMA16816(acc[i][j], a_[i], b_[j]);
        }
        __syncthreads();
    }

    const float invsq = 0.08838834764831845f;  // 1/sqrt(128)
    #pragma unroll
    for(int i=0;i<2;i++){
        int r = row0 + wr0 + i*16 + gid;
        #pragma unroll
        for(int j=0;j<4;j++){
            int c = col0 + wc0 + j*8 + 2*tig;
            float b0 = g_bqk[layer*PC + c], b1 = g_bqk[layer*PC + c + 1];
            *(__nv_bfloat162*)&g_pb[(size_t)r*PC + c] = __nv_bfloat162(
                __float2bfloat16((acc[i][j][0] + b0)*invsq),
                __float2bfloat16((acc[i][j][1] + b1)*invsq));
            *(__nv_bfloat162*)&g_pb[(size_t)(r+8)*PC + c] = __nv_bfloat162(
                __float2bfloat16((acc[i][j][2] + b0)*invsq),
                __float2bfloat16((acc[i][j][3] + b1)*invsq));
        }
    }
}

// ---------------- attention: plain-sum softmax (scores provably small) -------
__global__ __launch_bounds__(256) void attn_kernel(int parity)
{
    const float4* x4 = (const float4*)(parity ? g_xn : g_x);
    int warp = (blockIdx.x*blockDim.x + threadIdx.x) >> 5;
    int lane = threadIdx.x & 31;
    if(warp >= NN) return;
    int d = warp;

    const __nv_bfloat162* pb = (const __nv_bfloat162*)&g_pb[(size_t)d*PC];
    float4 p[HH];
    #pragma unroll
    for(int h=0;h<HH;h++){
        float2 f0 = __bfloat1622float2(pb[h*64 + lane*2]);
        float2 f1 = __bfloat1622float2(pb[h*64 + lane*2 + 1]);
        p[h] = make_float4(f0.x, f0.y, f1.x, f1.y);
    }

    int e0 = g_off[d], e1 = g_off[d+1];
    float den[HH];
    float4 y[HH];
    #pragma unroll
    for(int h=0;h<HH;h++){ den[h]=0.f; y[h]=make_float4(0.f,0.f,0.f,0.f); }

    for(int t=e0; t<e1; t++){
        int s = g_srcs[t];
        float4 xv = x4[(size_t)s*32 + lane];
        float dot[HH];
        #pragma unroll
        for(int h=0;h<HH;h++)
            dot[h] = p[h].x*xv.x + p[h].y*xv.y + p[h].z*xv.z + p[h].w*xv.w;
        #pragma unroll
        for(int h=0;h<HH;h++){
            #pragma unroll
            for(int o=16;o>0;o>>=1) dot[h] += __shfl_xor_sync(0xffffffffu, dot[h], o);
        }
        #pragma unroll
        for(int h=0;h<HH;h++){
            float ex = __expf(fminf(dot[h], 80.f));   // softmax shift-invariant; clamp = overflow guard
            den[h] += ex;
            y[h].x += ex*xv.x;
            y[h].y += ex*xv.y;
            y[h].z += ex*xv.z;
            y[h].w += ex*xv.w;
        }
    }

    size_t base = (size_t)d*PC;
    #pragma unroll
    for(int h=0;h<HH;h++){
        float r = (den[h] > 0.f) ? 1.f/den[h] : 0.f;
        float v0=y[h].x*r, v1=y[h].y*r, v2=y[h].z*r, v3=y[h].w*r;
        int c = h*CC + lane*4;
        __nv_bfloat16 h0=__float2bfloat16(v0), h1=__float2bfloat16(v1);
        __nv_bfloat16 h2=__float2bfloat16(v2), h3=__float2bfloat16(v3);
        *(__nv_bfloat162*)&g_yh[base+c]   = __nv_bfloat162(h0, h1);
        *(__nv_bfloat162*)&g_yh[base+c+2] = __nv_bfloat162(h2, h3);
        __nv_bfloat16 l0=__float2bfloat16(v0-__bfloat162float(h0));
        __nv_bfloat16 l1=__float2bfloat16(v1-__bfloat162float(h1));
        __nv_bfloat16 l2=__float2bfloat16(v2-__bfloat162float(h2));
        __nv_bfloat16 l3=__float2bfloat16(v3-__bfloat162float(h3));
        *(__nv_bfloat162*)&g_yl[base+c]   = __nv_bfloat162(l0, l1);
        *(__nv_bfloat162*)&g_yl[base+c+2] = __nv_bfloat162(l2, l3);
    }
}

// ---------------- GEMM B: out = [y|x] @ WB^T (+bias,+res) -> LN -> ReLU ------
// 128x128 tile, 512 threads (16 warps 4x4, warp tile 32x32); K=896 in 28 chunks
// of 32; 3-pass hi/lo with Bh refetch (caps regs); double-buffered cp.async,
// ONE barrier per stage; 2 CTAs/SM. Epilogue C fp32 [128][132] reuses smem.
#define GB_SEG 10240
#define GB_STAGE (4*GB_SEG)          // 40960
#define GB_SMEM (2*GB_STAGE)         // 81920
__global__ __launch_bounds__(512,2) void gemm_b(
    int layer, int parity,
    const float* __restrict__ bs, const float* __restrict__ lg, const float* __restrict__ lb)
{
    extern __shared__ char dsm[];
    __nv_bfloat16 (*Ah)[40] = (__nv_bfloat16(*)[40])(dsm);
    __nv_bfloat16 (*Al)[40] = (__nv_bfloat16(*)[40])(dsm + GB_SEG);
    __nv_bfloat16 (*Bh)[40] = (__nv_bfloat16(*)[40])(dsm + 2*GB_SEG);
    __nv_bfloat16 (*Bl)[40] = (__nv_bfloat16(*)[40])(dsm + 3*GB_SEG);

    const float* xold = parity ? g_xn : g_x;
    float*       xo   = parity ? g_x  : g_xn;
    int row0 = blockIdx.x * 128;
    int tid = threadIdx.x, warp = tid >> 5, lane = tid & 31;
    int wm = warp >> 2, wn = warp & 3;      // 4 x 4
    int wr0 = wm * 32, wc0 = wn * 32;
    int gid = lane >> 2, tig = lane & 3;

    float acc[2][4][4];
    #pragma unroll
    for(int i=0;i<2;i++)
        #pragma unroll
        for(int j=0;j<4;j++)
            #pragma unroll
            for(int t=0;t<4;t++) acc[i][j][t] = 0.f;

    int lr = tid >> 2;              // row 0..127
    int lc = (tid & 3) * 8;         // one 16B slot per thread per array
    unsigned stAh = smem_u32p(&Ah[lr][lc]);
    unsigned stAl = smem_u32p(&Al[lr][lc]);
    unsigned stBh = smem_u32p(&Bh[lr][lc]);
    unsigned stBl = smem_u32p(&Bl[lr][lc]);

    unsigned aAddrH[2], aAddrL[2], bAddrH[2], bAddrL[2];
    {
        int arow = lane & 15, ak = (lane >> 4) * 8;
        #pragma unroll
        for(int i=0;i<2;i++){
            aAddrH[i] = smem_u32p(&Ah[wr0 + i*16 + arow][ak]);
            aAddrL[i] = smem_u32p(&Al[wr0 + i*16 + arow][ak]);
        }
        int bcol = (lane & 7) + ((lane >> 4) << 3);
        int bk = ((lane >> 3) & 1) * 8;
        #pragma unroll
        for(int g=0; g<2; g++){
            bAddrH[g] = smem_u32p(&Bh[wc0 + g*16 + bcol][bk]);
            bAddrL[g] = smem_u32p(&Bl[wc0 + g*16 + bcol][bk]);
        }
    }

    // one stage: 4 cp.async of 16B per thread
    auto issue = [&](int s){
        int k0 = s * 32;
        unsigned so = (unsigned)(s & 1) * GB_STAGE;
        const __nv_bfloat16 *ah, *al;
        if(k0 < PC){
            ah = &g_yh[(size_t)(row0+lr)*PC + k0 + lc];
            al = &g_yl[(size_t)(row0+lr)*PC + k0 + lc];
        } else {
            ah = &g_xh[(size_t)(row0+lr)*CC + (k0 - PC) + lc];
            al = &g_xl[(size_t)(row0+lr)*CC + (k0 - PC) + lc];
        }
        const __nv_bfloat16* bhg = &g_WBh[((size_t)layer*CC + lr)*KB + k0 + lc];
        const __nv_bfloat16* blg = &g_WBl[((size_t)layer*CC + lr)*KB + k0 + lc];
        CPASYNC16(stAh + so, ah);
        CPASYNC16(stAl + so, al);
        CPASYNC16(stBh + so, bhg);
        CPASYNC16(stBl + so, blg);
        CPCOMMIT();
    };

    issue(0);
    for(int s=0; s<28; s++){
        CPWAIT(0);
        __syncthreads();                 // stage-s data visible; prev buffer free
        if(s < 27) issue(s+1);           // overlaps compute below
        unsigned bo = (unsigned)(s & 1) * GB_STAGE;

        #pragma unroll
        for(int ks=0; ks<32; ks+=16){
            unsigned a_[2][4], b_[4][2];
            // pass 1: Ah x Bh
            #pragma unroll
            for(int g=0; g<2; g++)
                LDSM_X4(b_[g*2][0], b_[g*2][1], b_[g*2+1][0], b_[g*2+1][1], bAddrH[g] + bo + ks*2);
            #pragma unroll
            for(int i=0;i<2;i++)
                LDSM_X4(a_[i][0], a_[i][1], a_[i][2], a_[i][3], aAddrH[i] + bo + ks*2);
            #pragma unroll
            for(int i=0;i<2;i++)
                #pragma unroll
                for(int j=0;j<4;j++)
                    MMA16816(acc[i][j], a_[i], b_[j]);
            // pass 2: Ah x Bl (reuse a_)
            #pragma unroll
            for(int g=0; g<2; g++)
                LDSM_X4(b_[g*2][0], b_[g*2][1], b_[g*2+1][0], b_[g*2+1][1], bAddrL[g] + bo + ks*2);
            #pragma unroll
            for(int i=0;i<2;i++)
                #pragma unroll
                for(int j=0;j<4;j++)
                    MMA16816(acc[i][j], a_[i], b_[j]);
            // pass 3: Al x Bh (refetch Bh into b_)
            #pragma unroll
            for(int i=0;i<2;i++)
                LDSM_X4(a_[i][0], a_[i][1], a_[i][2], a_[i][3], aAddrL[i] + bo + ks*2);
            #pragma unroll
            for(int g=0; g<2; g++)
                LDSM_X4(b_[g*2][0], b_[g*2][1], b_[g*2+1][0], b_[g*2+1][1], bAddrH[g] + bo + ks*2);
            #pragma unroll
            for(int i=0;i<2;i++)
                #pragma unroll
                for(int j=0;j<4;j++)
                    MMA16816(acc[i][j], a_[i], b_[j]);
        }
        __syncthreads();                 // done reading stage-s buffer
    }

    // dump accumulators to smem C (stride 132 floats)
    float* Csm = (float*)dsm;
    #pragma unroll
    for(int i=0;i<2;i++){
        int r = wr0 + i*16 + gid;
        #pragma unroll
        for(int j=0;j<4;j++){
            int c = wc0 + j*8 + 2*tig;
            Csm[r*132 + c]       = acc[i][j][0];
            Csm[r*132 + c + 1]   = acc[i][j][1];
            Csm[(r+8)*132 + c]   = acc[i][j][2];
            Csm[(r+8)*132 + c+1] = acc[i][j][3];
        }
    }
    __syncthreads();

    // epilogue: 4 threads per row, 32 channels each
    {
        int row = tid >> 2, part = tid & 3;
        int n = row0 + row;
        float* Crow = Csm + row*132 + part*32;
        float flag = (g_off[n+1] > g_off[n]) ? 1.f : 0.f;
        const float* xr = &xold[(size_t)n*CC + part*32];
        int cb = part*32;
        float s1 = 0.f;
        #pragma unroll 8
        for(int k=0;k<32;k++){
            int c = cb + k;
            float v = Crow[k] + bs[c] + flag*g_bvm[layer*CC + c] + xr[k];
            Crow[k] = v;
            s1 += v;
        }
        s1 += __shfl_xor_sync(0xffffffffu, s1, 1);
        s1 += __shfl_xor_sync(0xffffffffu, s1, 2);
        float mean = s1 * (1.f/CC);
        float s2 = 0.f;
        #pragma unroll 8
        for(int k=0;k<32;k++){ float dv = Crow[k]-mean; s2 += dv*dv; }
        s2 += __shfl_xor_sync(0xffffffffu, s2, 1);
        s2 += __shfl_xor_sync(0xffffffffu, s2, 2);
        float inv = rsqrtf(s2*(1.f/CC) + 1e-5f);
        #pragma unroll 4
        for(int k=0;k<32;k+=2){
            int c = cb + k;
            float y0 = (Crow[k]  -mean)*inv*lg[c]   + lb[c];
            float y1 = (Crow[k+1]-mean)*inv*lg[c+1] + lb[c+1];
            y0 = fmaxf(y0, 0.f); y1 = fmaxf(y1, 0.f);
            *(float2*)&xo[(size_t)n*CC + c] = make_float2(y0, y1);
            __nv_bfloat16 h0 = __float2bfloat16(y0), h1 = __float2bfloat16(y1);
            *(__nv_bfloat162*)&g_xh[(size_t)n*CC + c] = __nv_bfloat162(h0, h1);
            *(__nv_bfloat162*)&g_xl[(size_t)n*CC + c] = __nv_bfloat162(
                __float2bfloat16(y0 - __bfloat162float(h0)),
                __float2bfloat16(y1 - __bfloat162float(h1)));
        }
    }
}

// ---------------- output MLP on supernodes -----------------------------------
__global__ void mlp_kernel(int sel, const float* __restrict__ W, const float* __restrict__ b){
    const float* in  = sel ? g_m1 : g_x;
    float*       out = sel ? g_m2 : g_m1;
    __shared__ float row[CC];
    int g = blockIdx.x, c = threadIdx.x;
    row[c] = in[(size_t)g*CC + c];
    __syncthreads();
    float acc = b[c];
    const float* w = &W[(size_t)c*CC];
    #pragma unroll 8
    for(int k2=0;k2<CC;k2++) acc += row[k2]*w[k2];
    out[(size_t)g*CC + c] = fmaxf(acc, 0.f);
}

__global__ void final_kernel(const float* __restrict__ Wp, const float* __restrict__ bp,
                             float* __restrict__ out){
    int warp = (blockIdx.x*blockDim.x + threadIdx.x) >> 5;
    int lane = threadIdx.x & 31;
    if(warp >= GG) return;
    float a = 0.f;
    #pragma unroll
    for(int i=0;i<4;i++){
        int c = lane + 32*i;
        a += g_m2[(size_t)warp*CC + c] * Wp[c];
    }
    #pragma unroll
    for(int o=16;o>0;o>>=1) a += __shfl_xor_sync(0xffffffffu, a, o);
    if(lane==0) out[warp] = a + bp[0];
}

// ---------------- launch -----------------------------------------------------
extern "C" void kernel_launch(void* const* d_in, const int* in_sizes, int n_in,
                              void* d_out, int out_size)
{
    const int*   atoms = (const int*)d_in[0];
    const int*   ei    = (const int*)d_in[1];
    const int*   src   = ei;
    const int*   dstp  = ei + EE;
    const float* embd  = (const float*)d_in[2];
    const float* Wq    = (const float*)d_in[3];
    const float* bq    = (const float*)d_in[4];
    const float* Wk    = (const float*)d_in[5];
    const float* bk    = (const float*)d_in[6];  (void)bk; // softmax-invariant
    const float* Wv    = (const float*)d_in[7];
    const float* bv    = (const float*)d_in[8];
    const float* Ws    = (const float*)d_in[9];
    const float* bs    = (const float*)d_in[10];
    const float* lg    = (const float*)d_in[11];
    const float* lb    = (const float*)d_in[12];
    const float* Wlin  = (const float*)d_in[13];
    const float* blin  = (const float*)d_in[14];
    const float* Wp    = (const float*)d_in[15];
    const float* bp    = (const float*)d_in[16];
    float* out = (float*)d_out;

    cudaFuncSetAttribute(gemm_b, cudaFuncAttributeMaxDynamicSharedMemorySize, GB_SMEM);

    // order chosen so my 4th launch is gemm_p(l=0) (ncu target)
    prep_kernel<<<10282, 128>>>(Wq, Wk, Wv, Ws, bq, bv);           // 1
    embed_kernel<<<NN*CC/256, 256>>>(atoms, embd);                 // 2
    hist_kernel<<<EE/256, 256>>>(dstp);                            // 3
    gemm_p<<<dim3(PC/128, NN/128), 512>>>(0);                      // 4 <- ncu target
    scan_kernel<<<1, 1024>>>();                                    // 5
    scatter_kernel<<<EE/256, 256>>>(src, dstp);                    // 6
    attn_kernel<<<NN/8, 256>>>(0);                                 // 7
    gemm_b<<<NN/128, 512, GB_SMEM>>>(0, 0, bs, lg, lb);            // 8

    for(int l=1; l<LL; l++){
        int parity = l & 1;
        gemm_p<<<dim3(PC/128, NN/128), 512>>>(l);
        attn_kernel<<<NN/8, 256>>>(parity);
        gemm_b<<<NN/128, 512, GB_SMEM>>>(l, parity, bs + (size_t)l*CC,
                                         lg + (size_t)l*CC, lb + (size_t)l*CC);
    }

    mlp_kernel<<<GG, CC>>>(0, Wlin,         blin);
    mlp_kernel<<<GG, CC>>>(1, Wlin + CC*CC, blin + CC);
    final_kernel<<<GG*32/256, 256>>>(Wp, bp, out);
}

// round 14
// speedup vs baseline: 1.1881x; 1.0016x over previous
#include <cuda_runtime.h>
#include <cuda_fp16.h>
#include <math.h>

#define NN 32768
#define EE 131072
#define HH 6
#define CC 128
#define LL 6
#define GG 2048
#define PC 768      // p / y width (H*C)
#define KB 896      // gemm B K dim (768 y + 128 x)

// ---------------- scratch (device globals) -----------------------------------
__device__ float g_x[NN*CC];
__device__ float g_xn[NN*CC];
__device__ __half g_xh[NN*CC];        // fp16 hi of x
__device__ __half g_xl[NN*CC];        // fp16 lo of x
__device__ __half g_pb[NN*PC];        // p, fp16, 1/sqrt(C) folded
__device__ __half g_yh[NN*PC];        // aggregated y, fp16 hi
__device__ __half g_yl[NN*PC];        // fp16 lo
__device__ float g_score[EE*HH];      // exp(score) per CSR slot
__device__ __half g_WAh[LL*PC*CC];    // Wqk = Wk^T Wq per head, fp16
__device__ float g_bqk[LL*PC];
__device__ __half g_WBh[LL*CC*KB];    // [Wv/H | Ws^T] combined, fp16 hi
__device__ __half g_WBl[LL*CC*KB];    // fp16 lo
__device__ float g_bvm[LL*CC];        // mean_h bv
__device__ int   g_deg[NN];
__device__ int   g_cnt[NN];
__device__ int   g_off[NN+1];
__device__ int   g_srcs[EE];          // CSR-ordered source node ids
__device__ int   g_dstc[EE];          // CSR-ordered dst node ids
__device__ float g_m1[GG*CC];
__device__ float g_m2[GG*CC];

// ---------------- prep: fold weights + zero counters (single launch) ---------
__global__ void prep_kernel(
    const float* __restrict__ Wq, const float* __restrict__ Wk,
    const float* __restrict__ Wv, const float* __restrict__ Ws,
    const float* __restrict__ bq, const float* __restrict__ bv)
{
    int bid = blockIdx.x, tid = threadIdx.x;
    if(bid < 4608){
        // Wqk_h[c,c2] = sum_cc Wk[h*128+cc, c] * Wq[h*128+cc, c2]
        int l = bid / (HH*CC);
        int rem = bid % (HH*CC);
        int h = rem >> 7, c = rem & 127;
        __shared__ float wk[128];
        wk[tid] = Wk[((size_t)l*PC + h*CC + tid)*CC + c];
        __syncthreads();
        float acc = 0.f;
        const float* wqp = &Wq[((size_t)l*PC + h*CC)*CC + tid];
        #pragma unroll 8
        for(int cc=0; cc<CC; cc++) acc += wk[cc] * wqp[(size_t)cc*CC];
        g_WAh[((size_t)l*PC + h*CC + c)*CC + tid] = __float2half(acc);
    } else if(bid < 4644){
        int b2 = bid - 4608;
        int l = b2 / HH, h = b2 % HH;
        float acc = 0.f;
        for(int cc=0; cc<CC; cc++)
            acc += bq[l*PC + h*CC + cc] * Wk[((size_t)l*PC + h*CC + cc)*CC + tid];
        g_bqk[l*PC + h*CC + tid] = acc;
    } else if(bid < 10020){
        int idx = (bid-4644)*128 + tid;          // over LL*CC*KB
        int l = idx / (CC*KB);
        int j = (idx / KB) % CC;
        int c = idx % KB;
        float v;
        if(c < PC){
            int h = c >> 7, cp = c & 127;
            v = Wv[((size_t)l*PC + h*CC + j)*CC + cp] * (1.f/HH);
        } else {
            v = Ws[((size_t)l*CC + j)*CC + (c - PC)];
        }
        size_t o = ((size_t)l*CC + j)*KB + c;
        __half hi = __float2half(v);
        g_WBh[o] = hi;
        g_WBl[o] = __float2half(v - __half2float(hi));
    } else if(bid < 10276){
        int i = (bid-10020)*128 + tid;
        g_deg[i]=0; g_cnt[i]=0;
    } else {
        int i = (bid-10276)*128 + tid;           // LL*CC
        int l = i >> 7, j = i & 127;
        float a = 0.f;
        #pragma unroll
        for(int h=0;h<HH;h++) a += bv[l*PC + h*CC + j];
        g_bvm[i] = a * (1.f/HH);
    }
}

// ---------------- CSR build --------------------------------------------------
__global__ void hist_kernel(const int* __restrict__ dst){
    int e = blockIdx.x*blockDim.x + threadIdx.x;
    if(e < EE) atomicAdd(&g_deg[dst[e]], 1);
}
__global__ void scan_kernel(){
    __shared__ int sh[1024];
    __shared__ int sbase;
    int tid = threadIdx.x;
    if(tid==0){ sbase = 0; g_off[0] = 0; }
    __syncthreads();
    for(int chunk=0; chunk<NN/1024; chunk++){
        int idx = chunk*1024 + tid;
        sh[tid] = g_deg[idx];
        __syncthreads();
        for(int o=1;o<1024;o<<=1){
            int t = (tid>=o) ? sh[tid-o] : 0;
            __syncthreads();
            sh[tid] += t;
            __syncthreads();
        }
        g_off[idx+1] = sbase + sh[tid];
        __syncthreads();
        if(tid==1023) sbase += sh[1023];
        __syncthreads();
    }
}
__global__ void scatter_kernel(const int* __restrict__ src, const int* __restrict__ dst){
    int e = blockIdx.x*blockDim.x + threadIdx.x;
    if(e < EE){
        int d = dst[e];
        int pos = g_off[d] + atomicAdd(&g_cnt[d], 1);
        g_srcs[pos] = src[e];
        g_dstc[pos] = d;
    }
}

// ---------------- embedding (+ fp16 split) -----------------------------------
__global__ void embed_kernel(const int* __restrict__ atoms, const float* __restrict__ embd){
    int i = blockIdx.x*blockDim.x + threadIdx.x;
    int n = i >> 7, c = i & 127;
    float v = embd[atoms[n]*CC + c];
    g_x[i] = v;
    __half h = __float2half(v);
    g_xh[i] = h;
    g_xl[i] = __float2half(v - __half2float(h));
}

// ---------------- MMA / LDSM / cp.async macros --------------------------------
#define MMA16816(d, a, b) asm volatile( \
    "mma.sync.aligned.m16n8k16.row.col.f32.f16.f16.f32 " \
    "{%0,%1,%2,%3}, {%4,%5,%6,%7}, {%8,%9}, {%0,%1,%2,%3};" \
    : "+f"(d[0]),"+f"(d[1]),"+f"(d[2]),"+f"(d[3]) \
    : "r"(a[0]),"r"(a[1]),"r"(a[2]),"r"(a[3]), "r"(b[0]),"r"(b[1]))

#define LDSM_X4(R0,R1,R2,R3,A) asm volatile( \
    "ldmatrix.sync.aligned.m8n8.x4.shared.b16 {%0,%1,%2,%3}, [%4];" \
    : "=r"(R0),"=r"(R1),"=r"(R2),"=r"(R3) : "r"(A))

#define CPASYNC16(saddr, gptr) asm volatile( \
    "cp.async.cg.shared.global [%0], [%1], 16;" :: "r"(saddr), "l"(gptr))
#define CPCOMMIT() asm volatile("cp.async.commit_group;" ::: "memory")
#define CPWAIT(n)  asm volatile("cp.async.wait_group %0;" :: "n"(n) : "memory")

__device__ __forceinline__ unsigned smem_u32p(const void* p){
    return (unsigned)__cvta_generic_to_shared(p);
}

// ---------------- GEMM A: p = (x @ Wqk^T + bqk)/sqrt(C), fp16 ----------------
__global__ __launch_bounds__(512,2) void gemm_p(int layer)
{
    __shared__ __half sA[128][72], sB[128][72];
    int col0 = blockIdx.x * 128;
    int row0 = blockIdx.y * 128;
    int tid = threadIdx.x, warp = tid >> 5, lane = tid & 31;
    int wm = warp >> 2, wn = warp & 3;      // 4 x 4 warp grid
    int wr0 = wm * 32, wc0 = wn * 32;       // warp tile 32 x 32
    int gid = lane >> 2, tig = lane & 3;

    float acc[2][4][4];
    #pragma unroll
    for(int i=0;i<2;i++)
        #pragma unroll
        for(int j=0;j<4;j++)
            #pragma unroll
            for(int t=0;t<4;t++) acc[i][j][t] = 0.f;

    int lr = tid >> 2;
    int lc = (tid & 3) * 16;
    const __half* Ag = &g_xh[(size_t)(row0+lr)*CC + lc];
    const __half* Bg = &g_WAh[((size_t)layer*PC + col0 + lr)*CC + lc];

    unsigned aAddr[2], bAddr[2];
    #pragma unroll
    for(int i=0;i<2;i++)
        aAddr[i] = smem_u32p(&sA[wr0 + i*16 + (lane & 15)][(lane >> 4) * 8]);
    #pragma unroll
    for(int g=0; g<2; g++)
        bAddr[g] = smem_u32p(&sB[wc0 + g*16 + (lane & 7) + ((lane >> 4) << 3)][((lane >> 3) & 1) * 8]);

    #pragma unroll
    for(int kit=0; kit<2; kit++){
        int k0 = kit * 64;
        #pragma unroll
        for(int q=0;q<2;q++){
            *(uint4*)&sA[lr][lc + 8*q] = *(const uint4*)(Ag + k0 + 8*q);
            *(uint4*)&sB[lr][lc + 8*q] = *(const uint4*)(Bg + k0 + 8*q);
        }
        __syncthreads();
        #pragma unroll
        for(int ks=0; ks<64; ks+=16){
            unsigned a_[2][4], b_[4][2];
            #pragma unroll
            for(int i=0;i<2;i++)
                LDSM_X4(a_[i][0], a_[i][1], a_[i][2], a_[i][3], aAddr[i] + ks*2);
            #pragma unroll
            for(int g=0; g<2; g++)
                LDSM_X4(b_[g*2][0], b_[g*2][1], b_[g*2+1][0], b_[g*2+1][1], bAddr[g] + ks*2);
            #pragma unroll
            for(int i=0;i<2;i++)
                #pragma unroll
                for(int j=0;j<4;j++)
                    MMA16816(acc[i][j], a_[i], b_[j]);
        }
        __syncthreads();
    }

    const float invsq = 0.08838834764831845f;  // 1/sqrt(128)
    #pragma unroll
    for(int i=0;i<2;i++){
        int r = row0 + wr0 + i*16 + gid;
        #pragma unroll
        for(int j=0;j<4;j++){
            int c = col0 + wc0 + j*8 + 2*tig;
            float b0 = g_bqk[layer*PC + c], b1 = g_bqk[layer*PC + c + 1];
            *(__half2*)&g_pb[(size_t)r*PC + c] =
                __floats2half2_rn((acc[i][j][0] + b0)*invsq, (acc[i][j][1] + b1)*invsq);
            *(__half2*)&g_pb[(size_t)(r+8)*PC + c] =
                __floats2half2_rn((acc[i][j][2] + b0)*invsq, (acc[i][j][3] + b1)*invsq);
        }
    }
}

// ---------------- attention phase 1: warp per edge, exp(score) ---------------
__global__ __launch_bounds__(256) void score_kernel(int parity)
{
    const float4* x4 = (const float4*)(parity ? g_xn : g_x);
    int w = (blockIdx.x*blockDim.x + threadIdx.x) >> 5;   // CSR slot
    int lane = threadIdx.x & 31;
    if(w >= EE) return;
    int s = g_srcs[w], d = g_dstc[w];

    float4 xv = x4[(size_t)s*32 + lane];
    const __half2* pb = (const __half2*)&g_pb[(size_t)d*PC];
    float dot[HH];
    #pragma unroll
    for(int h=0;h<HH;h++){
        float2 f0 = __half22float2(pb[h*64 + lane*2]);
        float2 f1 = __half22float2(pb[h*64 + lane*2 + 1]);
        dot[h] = f0.x*xv.x + f0.y*xv.y + f1.x*xv.z + f1.y*xv.w;
    }
    #pragma unroll
    for(int h=0;h<HH;h++){
        #pragma unroll
        for(int o=16;o>0;o>>=1) dot[h] += __shfl_xor_sync(0xffffffffu, dot[h], o);
    }
    float myv = dot[0];
    myv = (lane==1)?dot[1]:myv;
    myv = (lane==2)?dot[2]:myv;
    myv = (lane==3)?dot[3]:myv;
    myv = (lane==4)?dot[4]:myv;
    myv = (lane==5)?dot[5]:myv;
    if(lane < HH)
        g_score[(size_t)w*HH + lane] = __expf(fminf(myv, 80.f));
}

// ---------------- attention phase 2: warp per node, aggregate (no shuffles) --
__global__ __launch_bounds__(256) void agg_kernel(int parity)
{
    const float4* x4 = (const float4*)(parity ? g_xn : g_x);
    int warp = (blockIdx.x*blockDim.x + threadIdx.x) >> 5;
    int lane = threadIdx.x & 31;
    if(warp >= NN) return;
    int d = warp;

    int e0 = g_off[d], e1 = g_off[d+1];
    float den[HH];
    float4 y[HH];
    #pragma unroll
    for(int h=0;h<HH;h++){ den[h]=0.f; y[h]=make_float4(0.f,0.f,0.f,0.f); }

    for(int t=e0; t<e1; t++){
        int s = g_srcs[t];
        float4 xv = x4[(size_t)s*32 + lane];
        const float* sc = &g_score[(size_t)t*HH];
        #pragma unroll
        for(int h=0;h<HH;h++){
            float ex = sc[h];             // broadcast load (same addr warp-wide)
            den[h] += ex;
            y[h].x += ex*xv.x;
            y[h].y += ex*xv.y;
            y[h].z += ex*xv.z;
            y[h].w += ex*xv.w;
        }
    }

    size_t base = (size_t)d*PC;
    #pragma unroll
    for(int h=0;h<HH;h++){
        float r = (den[h] > 0.f) ? 1.f/den[h] : 0.f;
        float v0=y[h].x*r, v1=y[h].y*r, v2=y[h].z*r, v3=y[h].w*r;
        int c = h*CC + lane*4;
        __half h0=__float2half(v0), h1=__float2half(v1);
        __half h2=__float2half(v2), h3=__float2half(v3);
        *(__half2*)&g_yh[base+c]   = __half2(h0, h1);
        *(__half2*)&g_yh[base+c+2] = __half2(h2, h3);
        *(__half2*)&g_yl[base+c]   = __half2(
            __float2half(v0-__half2float(h0)), __float2half(v1-__half2float(h1)));
        *(__half2*)&g_yl[base+c+2] = __half2(
            __float2half(v2-__half2float(h2)), __float2half(v3-__half2float(h3)));
    }
}

// ---------------- GEMM B: out = [y|x] @ WB^T, fp16 3-pass hi/lo --------------
// 128x128 tile, 512 threads; K=896 in 28 chunks of 32; double-buffered
// cp.async, 2 CTAs/SM; epilogue C fp32 [128][132] reuses smem.
#define GB_SEG 10240
#define GB_STAGE (4*GB_SEG)          // 40960
#define GB_SMEM (2*GB_STAGE)         // 81920
__global__ __launch_bounds__(512,2) void gemm_b(
    int layer, int parity,
    const float* __restrict__ bs, const float* __restrict__ lg, const float* __restrict__ lb)
{
    extern __shared__ char dsm[];
    __half (*Ah)[40] = (__half(*)[40])(dsm);
    __half (*Al)[40] = (__half(*)[40])(dsm + GB_SEG);
    __half (*Bh)[40] = (__half(*)[40])(dsm + 2*GB_SEG);
    __half (*Bl)[40] = (__half(*)[40])(dsm + 3*GB_SEG);

    const float* xold = parity ? g_xn : g_x;
    float*       xo   = parity ? g_x  : g_xn;
    int row0 = blockIdx.x * 128;
    int tid = threadIdx.x, warp = tid >> 5, lane = tid & 31;
    int wm = warp >> 2, wn = warp & 3;      // 4 x 4
    int wr0 = wm * 32, wc0 = wn * 32;
    int gid = lane >> 2, tig = lane & 3;

    float acc[2][4][4];
    #pragma unroll
    for(int i=0;i<2;i++)
        #pragma unroll
        for(int j=0;j<4;j++)
            #pragma unroll
            for(int t=0;t<4;t++) acc[i][j][t] = 0.f;

    int lr = tid >> 2;              // row 0..127
    int lc = (tid & 3) * 8;         // one 16B slot per thread per array
    unsigned stAh = smem_u32p(&Ah[lr][lc]);
    unsigned stAl = smem_u32p(&Al[lr][lc]);
    unsigned stBh = smem_u32p(&Bh[lr][lc]);
    unsigned stBl = smem_u32p(&Bl[lr][lc]);

    unsigned aAddrH[2], aAddrL[2], bAddrH[2], bAddrL[2];
    {
        int arow = lane & 15, ak = (lane >> 4) * 8;
        #pragma unroll
        for(int i=0;i<2;i++){
            aAddrH[i] = smem_u32p(&Ah[wr0 + i*16 + arow][ak]);
            aAddrL[i] = smem_u32p(&Al[wr0 + i*16 + arow][ak]);
        }
        int bcol = (lane & 7) + ((lane >> 4) << 3);
        int bk = ((lane >> 3) & 1) * 8;
        #pragma unroll
        for(int g=0; g<2; g++){
            bAddrH[g] = smem_u32p(&Bh[wc0 + g*16 + bcol][bk]);
            bAddrL[g] = smem_u32p(&Bl[wc0 + g*16 + bcol][bk]);
        }
    }

    auto issue = [&](int s){
        int k0 = s * 32;
        unsigned so = (unsigned)(s & 1) * GB_STAGE;
        const __half *ah, *al;
        if(k0 < PC){
            ah = &g_yh[(size_t)(row0+lr)*PC + k0 + lc];
            al = &g_yl[(size_t)(row0+lr)*PC + k0 + lc];
        } else {
            ah = &g_xh[(size_t)(row0+lr)*CC + (k0 - PC) + lc];
            al = &g_xl[(size_t)(row0+lr)*CC + (k0 - PC) + lc];
        }
        const __half* bhg = &g_WBh[((size_t)layer*CC + lr)*KB + k0 + lc];
        const __half* blg = &g_WBl[((size_t)layer*CC + lr)*KB + k0 + lc];
        CPASYNC16(stAh + so, ah);
        CPASYNC16(stAl + so, al);
        CPASYNC16(stBh + so, bhg);
        CPASYNC16(stBl + so, blg);
        CPCOMMIT();
    };

    issue(0);
    for(int s=0; s<28; s++){
        CPWAIT(0);
        __syncthreads();
        if(s < 27) issue(s+1);
        unsigned bo = (unsigned)(s & 1) * GB_STAGE;

        #pragma unroll
        for(int ks=0; ks<32; ks+=16){
            unsigned a_[2][4], b_[4][2];
            // pass 1: Ah x Bh
            #pragma unroll
            for(int g=0; g<2; g++)
                LDSM_X4(b_[g*2][0], b_[g*2][1], b_[g*2+1][0], b_[g*2+1][1], bAddrH[g] + bo + ks*2);
            #pragma unroll
            for(int i=0;i<2;i++)
                LDSM_X4(a_[i][0], a_[i][1], a_[i][2], a_[i][3], aAddrH[i] + bo + ks*2);
            #pragma unroll
            for(int i=0;i<2;i++)
                #pragma unroll
                for(int j=0;j<4;j++)
                    MMA16816(acc[i][j], a_[i], b_[j]);
            // pass 2: Ah x Bl
            #pragma unroll
            for(int g=0; g<2; g++)
                LDSM_X4(b_[g*2][0], b_[g*2][1], b_[g*2+1][0], b_[g*2+1][1], bAddrL[g] + bo + ks*2);
            #pragma unroll
            for(int i=0;i<2;i++)
                #pragma unroll
                for(int j=0;j<4;j++)
                    MMA16816(acc[i][j], a_[i], b_[j]);
            // pass 3: Al x Bh (refetch Bh)
            #pragma unroll
            for(int i=0;i<2;i++)
                LDSM_X4(a_[i][0], a_[i][1], a_[i][2], a_[i][3], aAddrL[i] + bo + ks*2);
            #pragma unroll
            for(int g=0; g<2; g++)
                LDSM_X4(b_[g*2][0], b_[g*2][1], b_[g*2+1][0], b_[g*2+1][1], bAddrH[g] + bo + ks*2);
            #pragma unroll
            for(int i=0;i<2;i++)
                #pragma unroll
                for(int j=0;j<4;j++)
                    MMA16816(acc[i][j], a_[i], b_[j]);
        }
        __syncthreads();
    }

    // dump accumulators to smem C (stride 132 floats)
    float* Csm = (float*)dsm;
    #pragma unroll
    for(int i=0;i<2;i++){
        int r = wr0 + i*16 + gid;
        #pragma unroll
        for(int j=0;j<4;j++){
            int c = wc0 + j*8 + 2*tig;
            Csm[r*132 + c]       = acc[i][j][0];
            Csm[r*132 + c + 1]   = acc[i][j][1];
            Csm[(r+8)*132 + c]   = acc[i][j][2];
            Csm[(r+8)*132 + c+1] = acc[i][j][3];
        }
    }
    __syncthreads();

    // epilogue: 4 threads per row, 32 channels each
    {
        int row = tid >> 2, part = tid & 3;
        int n = row0 + row;
        float* Crow = Csm + row*132 + part*32;
        float flag = (g_off[n+1] > g_off[n]) ? 1.f : 0.f;
        const float* xr = &xold[(size_t)n*CC + part*32];
        int cb = part*32;
        float s1 = 0.f;
        #pragma unroll 8
        for(int k=0;k<32;k++){
            int c = cb + k;
            float v = Crow[k] + bs[c] + flag*g_bvm[layer*CC + c] + xr[k];
            Crow[k] = v;
            s1 += v;
        }
        s1 += __shfl_xor_sync(0xffffffffu, s1, 1);
        s1 += __shfl_xor_sync(0xffffffffu, s1, 2);
        float mean = s1 * (1.f/CC);
        float s2 = 0.f;
        #pragma unroll 8
        for(int k=0;k<32;k++){ float dv = Crow[k]-mean; s2 += dv*dv; }
        s2 += __shfl_xor_sync(0xffffffffu, s2, 1);
        s2 += __shfl_xor_sync(0xffffffffu, s2, 2);
        float inv = rsqrtf(s2*(1.f/CC) + 1e-5f);
        #pragma unroll 4
        for(int k=0;k<32;k+=2){
            int c = cb + k;
            float y0 = (Crow[k]  -mean)*inv*lg[c]   + lb[c];
            float y1 = (Crow[k+1]-mean)*inv*lg[c+1] + lb[c+1];
            y0 = fmaxf(y0, 0.f); y1 = fmaxf(y1, 0.f);
            *(float2*)&xo[(size_t)n*CC + c] = make_float2(y0, y1);
            __half h0 = __float2half(y0), h1 = __float2half(y1);
            *(__half2*)&g_xh[(size_t)n*CC + c] = __half2(h0, h1);
            *(__half2*)&g_xl[(size_t)n*CC + c] = __half2(
                __float2half(y0 - __half2float(h0)),
                __float2half(y1 - __half2float(h1)));
        }
    }
}

// ---------------- output MLP on supernodes -----------------------------------
__global__ void mlp_kernel(int sel, const float* __restrict__ W, const float* __restrict__ b){
    const float* in  = sel ? g_m1 : g_x;
    float*       out = sel ? g_m2 : g_m1;
    __shared__ float row[CC];
    int g = blockIdx.x, c = threadIdx.x;
    row[c] = in[(size_t)g*CC + c];
    __syncthreads();
    float acc = b[c];
    const float* w = &W[(size_t)c*CC];
    #pragma unroll 8
    for(int k2=0;k2<CC;k2++) acc += row[k2]*w[k2];
    out[(size_t)g*CC + c] = fmaxf(acc, 0.f);
}

__global__ void final_kernel(const float* __restrict__ Wp, const float* __restrict__ bp,
                             float* __restrict__ out){
    int warp = (blockIdx.x*blockDim.x + threadIdx.x) >> 5;
    int lane = threadIdx.x & 31;
    if(warp >= GG) return;
    float a = 0.f;
    #pragma unroll
    for(int i=0;i<4;i++){
        int c = lane + 32*i;
        a += g_m2[(size_t)warp*CC + c] * Wp[c];
    }
    #pragma unroll
    for(int o=16;o>0;o>>=1) a += __shfl_xor_sync(0xffffffffu, a, o);
    if(lane==0) out[warp] = a + bp[0];
}

// ---------------- launch -----------------------------------------------------
extern "C" void kernel_launch(void* const* d_in, const int* in_sizes, int n_in,
                              void* d_out, int out_size)
{
    const int*   atoms = (const int*)d_in[0];
    const int*   ei    = (const int*)d_in[1];
    const int*   src   = ei;
    const int*   dstp  = ei + EE;
    const float* embd  = (const float*)d_in[2];
    const float* Wq    = (const float*)d_in[3];
    const float* bq    = (const float*)d_in[4];
    const float* Wk    = (const float*)d_in[5];
    const float* bk    = (const float*)d_in[6];  (void)bk; // softmax-invariant
    const float* Wv    = (const float*)d_in[7];
    const float* bv    = (const float*)d_in[8];
    const float* Ws    = (const float*)d_in[9];
    const float* bs    = (const float*)d_in[10];
    const float* lg    = (const float*)d_in[11];
    const float* lb    = (const float*)d_in[12];
    const float* Wlin  = (const float*)d_in[13];
    const float* blin  = (const float*)d_in[14];
    const float* Wp    = (const float*)d_in[15];
    const float* bp    = (const float*)d_in[16];
    float* out = (float*)d_out;

    cudaFuncSetAttribute(gemm_b, cudaFuncAttributeMaxDynamicSharedMemorySize, GB_SMEM);

    // order chosen so my 4th launch is gemm_p(l=0) (ncu target)
    prep_kernel<<<10282, 128>>>(Wq, Wk, Wv, Ws, bq, bv);           // 1
    embed_kernel<<<NN*CC/256, 256>>>(atoms, embd);                 // 2
    hist_kernel<<<EE/256, 256>>>(dstp);                            // 3
    gemm_p<<<dim3(PC/128, NN/128), 512>>>(0);                      // 4 <- ncu target
    scan_kernel<<<1, 1024>>>();                                    // 5
    scatter_kernel<<<EE/256, 256>>>(src, dstp);                    // 6
    score_kernel<<<EE*32/256, 256>>>(0);                           // 7
    agg_kernel<<<NN/8, 256>>>(0);                                  // 8
    gemm_b<<<NN/128, 512, GB_SMEM>>>(0, 0, bs, lg, lb);            // 9

    for(int l=1; l<LL; l++){
        int parity = l & 1;
        gemm_p<<<dim3(PC/128, NN/128), 512>>>(l);
        score_kernel<<<EE*32/256, 256>>>(parity);
        agg_kernel<<<NN/8, 256>>>(parity);
        gemm_b<<<NN/128, 512, GB_SMEM>>>(l, parity, bs + (size_t)l*CC,
                                         lg + (size_t)l*CC, lb + (size_t)l*CC);
    }

    mlp_kernel<<<GG, CC>>>(0, Wlin,         blin);
    mlp_kernel<<<GG, CC>>>(1, Wlin + CC*CC, blin + CC);
    final_kernel<<<GG*32/256, 256>>>(Wp, bp, out);
}

// round 15
// speedup vs baseline: 1.2380x; 1.0420x over previous
#include <cuda_runtime.h>
#include <cuda_fp16.h>
#include <math.h>

#define NN 32768
#define EE 131072
#define HH 6
#define CC 128
#define LL 6
#define GG 2048
#define PC 768      // p / y width (H*C)
#define KB 896      // gemm B K dim (768 y + 128 x)

// ---------------- scratch (device globals) -----------------------------------
__device__ float g_x[NN*CC];
__device__ float g_xn[NN*CC];
__device__ __half g_xh[NN*CC];        // fp16 hi of x
__device__ __half g_xl[NN*CC];        // fp16 lo of x
__device__ __half g_pb[NN*PC];        // p, fp16, 1/sqrt(C) folded
__device__ __half g_yh[NN*PC];        // aggregated y, fp16 hi
__device__ __half g_yl[NN*PC];        // fp16 lo
__device__ float g_score[EE*HH];      // exp(score) per CSR slot
__device__ __half g_WAh[LL*PC*CC];    // Wqk = Wk^T Wq per head, fp16
__device__ float g_bqk[LL*PC];
__device__ __half g_WBh[LL*CC*KB];    // [Wv/H | Ws^T] combined, fp16 hi
__device__ __half g_WBl[LL*CC*KB];    // fp16 lo
__device__ float g_bvm[LL*CC];        // mean_h bv
__device__ int   g_deg[NN];
__device__ int   g_cnt[NN];
__device__ int   g_off[NN+1];
__device__ int   g_bsum[32];
__device__ int   g_boff[32];
__device__ int   g_srcs[EE];          // CSR-ordered source node ids
__device__ int   g_dstc[EE];          // CSR-ordered dst node ids
__device__ float g_m1[GG*CC];
__device__ float g_m2[GG*CC];

// ---------------- prep: fold weights + zero counters (single launch) ---------
__global__ void prep_kernel(
    const float* __restrict__ Wq, const float* __restrict__ Wk,
    const float* __restrict__ Wv, const float* __restrict__ Ws,
    const float* __restrict__ bq, const float* __restrict__ bv)
{
    int bid = blockIdx.x, tid = threadIdx.x;
    if(bid < 4608){
        // Wqk_h[c,c2] = sum_cc Wk[h*128+cc, c] * Wq[h*128+cc, c2]
        int l = bid / (HH*CC);
        int rem = bid % (HH*CC);
        int h = rem >> 7, c = rem & 127;
        __shared__ float wk[128];
        wk[tid] = Wk[((size_t)l*PC + h*CC + tid)*CC + c];
        __syncthreads();
        float acc = 0.f;
        const float* wqp = &Wq[((size_t)l*PC + h*CC)*CC + tid];
        #pragma unroll 8
        for(int cc=0; cc<CC; cc++) acc += wk[cc] * wqp[(size_t)cc*CC];
        g_WAh[((size_t)l*PC + h*CC + c)*CC + tid] = __float2half(acc);
    } else if(bid < 4644){
        int b2 = bid - 4608;
        int l = b2 / HH, h = b2 % HH;
        float acc = 0.f;
        for(int cc=0; cc<CC; cc++)
            acc += bq[l*PC + h*CC + cc] * Wk[((size_t)l*PC + h*CC + cc)*CC + tid];
        g_bqk[l*PC + h*CC + tid] = acc;
    } else if(bid < 10020){
        int idx = (bid-4644)*128 + tid;          // over LL*CC*KB
        int l = idx / (CC*KB);
        int j = (idx / KB) % CC;
        int c = idx % KB;
        float v;
        if(c < PC){
            int h = c >> 7, cp = c & 127;
            v = Wv[((size_t)l*PC + h*CC + j)*CC + cp] * (1.f/HH);
        } else {
            v = Ws[((size_t)l*CC + j)*CC + (c - PC)];
        }
        size_t o = ((size_t)l*CC + j)*KB + c;
        __half hi = __float2half(v);
        g_WBh[o] = hi;
        g_WBl[o] = __float2half(v - __half2float(hi));
    } else if(bid < 10276){
        int i = (bid-10020)*128 + tid;
        g_deg[i]=0; g_cnt[i]=0;
    } else {
        int i = (bid-10276)*128 + tid;           // LL*CC
        int l = i >> 7, j = i & 127;
        float a = 0.f;
        #pragma unroll
        for(int h=0;h<HH;h++) a += bv[l*PC + h*CC + j];
        g_bvm[i] = a * (1.f/HH);
    }
}

// ---------------- CSR build --------------------------------------------------
__global__ void hist_kernel(const int* __restrict__ dst){
    int e = blockIdx.x*blockDim.x + threadIdx.x;
    if(e < EE) atomicAdd(&g_deg[dst[e]], 1);
}
// parallel scan phase 1: per-block inclusive scan + block sums
__global__ void scan1_kernel(){
    __shared__ int sh[1024];
    int b = blockIdx.x, tid = threadIdx.x;
    int idx = b*1024 + tid;
    sh[tid] = g_deg[idx];
    __syncthreads();
    for(int o=1;o<1024;o<<=1){
        int t = (tid>=o) ? sh[tid-o] : 0;
        __syncthreads();
        sh[tid] += t;
        __syncthreads();
    }
    g_off[idx+1] = sh[tid];
    if(tid==1023) g_bsum[b] = sh[1023];
}
// phase 2: exclusive scan of 32 block sums (one warp)
__global__ void scan2_kernel(){
    int tid = threadIdx.x;
    int v = g_bsum[tid];
    int inc = v;
    #pragma unroll
    for(int o=1;o<32;o<<=1){
        int t = __shfl_up_sync(0xffffffffu, inc, o);
        if(tid >= o) inc += t;
    }
    g_boff[tid] = inc - v;
    if(tid==0) g_off[0] = 0;
}
// phase 3: add block offsets
__global__ void scan3_kernel(){
    int idx = blockIdx.x*blockDim.x + threadIdx.x;
    g_off[idx+1] += g_boff[idx >> 10];
}
__global__ void scatter_kernel(const int* __restrict__ src, const int* __restrict__ dst){
    int e = blockIdx.x*blockDim.x + threadIdx.x;
    if(e < EE){
        int d = dst[e];
        int pos = g_off[d] + atomicAdd(&g_cnt[d], 1);
        g_srcs[pos] = src[e];
        g_dstc[pos] = d;
    }
}

// ---------------- embedding (+ fp16 split) -----------------------------------
__global__ void embed_kernel(const int* __restrict__ atoms, const float* __restrict__ embd){
    int i = blockIdx.x*blockDim.x + threadIdx.x;
    int n = i >> 7, c = i & 127;
    float v = embd[atoms[n]*CC + c];
    g_x[i] = v;
    __half h = __float2half(v);
    g_xh[i] = h;
    g_xl[i] = __float2half(v - __half2float(h));
}

// ---------------- MMA / LDSM / cp.async macros --------------------------------
#define MMA16816(d, a, b) asm volatile( \
    "mma.sync.aligned.m16n8k16.row.col.f32.f16.f16.f32 " \
    "{%0,%1,%2,%3}, {%4,%5,%6,%7}, {%8,%9}, {%0,%1,%2,%3};" \
    : "+f"(d[0]),"+f"(d[1]),"+f"(d[2]),"+f"(d[3]) \
    : "r"(a[0]),"r"(a[1]),"r"(a[2]),"r"(a[3]), "r"(b[0]),"r"(b[1]))

#define LDSM_X4(R0,R1,R2,R3,A) asm volatile( \
    "ldmatrix.sync.aligned.m8n8.x4.shared.b16 {%0,%1,%2,%3}, [%4];" \
    : "=r"(R0),"=r"(R1),"=r"(R2),"=r"(R3) : "r"(A))

#define CPASYNC16(saddr, gptr) asm volatile( \
    "cp.async.cg.shared.global [%0], [%1], 16;" :: "r"(saddr), "l"(gptr))
#define CPCOMMIT() asm volatile("cp.async.commit_group;" ::: "memory")
#define CPWAIT(n)  asm volatile("cp.async.wait_group %0;" :: "n"(n) : "memory")

__device__ __forceinline__ unsigned smem_u32p(const void* p){
    return (unsigned)__cvta_generic_to_shared(p);
}

// ---------------- GEMM A: p = (x @ Wqk^T + bqk)/sqrt(C), fp16 ----------------
// 128x128 CTA tile, 512 threads; K=128 in 2 chunks, DOUBLE-BUFFERED cp.async.
// dyn smem: A0 | A1 | B0 | B1, each 128x72 half = 18432 B -> 73728 B.
#define GP_SEG 18432
#define GP_SMEM (4*GP_SEG)
__global__ __launch_bounds__(512,2) void gemm_p(int layer)
{
    extern __shared__ char dsm[];
    __half (*A0)[72] = (__half(*)[72])(dsm);
    __half (*B0)[72] = (__half(*)[72])(dsm + 2*GP_SEG);
    int col0 = blockIdx.x * 128;
    int row0 = blockIdx.y * 128;
    int tid = threadIdx.x, warp = tid >> 5, lane = tid & 31;
    int wm = warp >> 2, wn = warp & 3;      // 4 x 4 warp grid
    int wr0 = wm * 32, wc0 = wn * 32;       // warp tile 32 x 32
    int gid = lane >> 2, tig = lane & 3;

    float acc[2][4][4];
    #pragma unroll
    for(int i=0;i<2;i++)
        #pragma unroll
        for(int j=0;j<4;j++)
            #pragma unroll
            for(int t=0;t<4;t++) acc[i][j][t] = 0.f;

    int lr = tid >> 2;
    int lc = (tid & 3) * 16;
    const __half* Ag = &g_xh[(size_t)(row0+lr)*CC + lc];
    const __half* Bg = &g_WAh[((size_t)layer*PC + col0 + lr)*CC + lc];
    unsigned stA = smem_u32p(&A0[lr][lc]);
    unsigned stB = smem_u32p(&B0[lr][lc]);

    // issue both K-chunks up front (separate commit groups)
    #pragma unroll
    for(int kit=0; kit<2; kit++){
        int k0 = kit * 64;
        unsigned so = (unsigned)kit * GP_SEG;
        CPASYNC16(stA + so,      Ag + k0);
        CPASYNC16(stA + so + 16, Ag + k0 + 8);
        CPASYNC16(stB + so,      Bg + k0);
        CPASYNC16(stB + so + 16, Bg + k0 + 8);
        CPCOMMIT();
    }

    unsigned aAddr[2], bAddr[2];
    #pragma unroll
    for(int i=0;i<2;i++)
        aAddr[i] = smem_u32p(&A0[wr0 + i*16 + (lane & 15)][(lane >> 4) * 8]);
    #pragma unroll
    for(int g=0; g<2; g++)
        bAddr[g] = smem_u32p(&B0[wc0 + g*16 + (lane & 7) + ((lane >> 4) << 3)][((lane >> 3) & 1) * 8]);

    #pragma unroll
    for(int kit=0; kit<2; kit++){
        if(kit == 0) CPWAIT(1); else CPWAIT(0);
        __syncthreads();
        unsigned so = (unsigned)kit * GP_SEG;
        #pragma unroll
        for(int ks=0; ks<64; ks+=16){
            unsigned a_[2][4], b_[4][2];
            #pragma unroll
            for(int i=0;i<2;i++)
                LDSM_X4(a_[i][0], a_[i][1], a_[i][2], a_[i][3], aAddr[i] + so + ks*2);
            #pragma unroll
            for(int g=0; g<2; g++)
                LDSM_X4(b_[g*2][0], b_[g*2][1], b_[g*2+1][0], b_[g*2+1][1], bAddr[g] + so + ks*2);
            #pragma unroll
            for(int i=0;i<2;i++)
                #pragma unroll
                for(int j=0;j<4;j++)
                    MMA16816(acc[i][j], a_[i], b_[j]);
        }
    }

    const float invsq = 0.08838834764831845f;  // 1/sqrt(128)
    #pragma unroll
    for(int i=0;i<2;i++){
        int r = row0 + wr0 + i*16 + gid;
        #pragma unroll
        for(int j=0;j<4;j++){
            int c = col0 + wc0 + j*8 + 2*tig;
            float b0 = g_bqk[layer*PC + c], b1 = g_bqk[layer*PC + c + 1];
            *(__half2*)&g_pb[(size_t)r*PC + c] =
                __floats2half2_rn((acc[i][j][0] + b0)*invsq, (acc[i][j][1] + b1)*invsq);
            *(__half2*)&g_pb[(size_t)(r+8)*PC + c] =
                __floats2half2_rn((acc[i][j][2] + b0)*invsq, (acc[i][j][3] + b1)*invsq);
        }
    }
}

// ---------------- attention phase 1: warp per edge, exp(score) ---------------
__global__ __launch_bounds__(256) void score_kernel(int parity)
{
    const float4* x4 = (const float4*)(parity ? g_xn : g_x);
    int w = (blockIdx.x*blockDim.x + threadIdx.x) >> 5;   // CSR slot
    int lane = threadIdx.x & 31;
    if(w >= EE) return;
    int s = g_srcs[w], d = g_dstc[w];

    float4 xv = x4[(size_t)s*32 + lane];
    const __half2* pb = (const __half2*)&g_pb[(size_t)d*PC];
    float dot[HH];
    #pragma unroll
    for(int h=0;h<HH;h++){
        float2 f0 = __half22float2(pb[h*64 + lane*2]);
        float2 f1 = __half22float2(pb[h*64 + lane*2 + 1]);
        dot[h] = f0.x*xv.x + f0.y*xv.y + f1.x*xv.z + f1.y*xv.w;
    }
    #pragma unroll
    for(int h=0;h<HH;h++){
        #pragma unroll
        for(int o=16;o>0;o>>=1) dot[h] += __shfl_xor_sync(0xffffffffu, dot[h], o);
    }
    float myv = dot[0];
    myv = (lane==1)?dot[1]:myv;
    myv = (lane==2)?dot[2]:myv;
    myv = (lane==3)?dot[3]:myv;
    myv = (lane==4)?dot[4]:myv;
    myv = (lane==5)?dot[5]:myv;
    if(lane < HH)
        g_score[(size_t)w*HH + lane] = __expf(fminf(myv, 80.f));
}

// ---------------- attention phase 2: warp per node, aggregate (no shuffles) --
__global__ __launch_bounds__(256) void agg_kernel(int parity)
{
    const float4* x4 = (const float4*)(parity ? g_xn : g_x);
    int warp = (blockIdx.x*blockDim.x + threadIdx.x) >> 5;
    int lane = threadIdx.x & 31;
    if(warp >= NN) return;
    int d = warp;

    int e0 = g_off[d], e1 = g_off[d+1];
    float den[HH];
    float4 y[HH];
    #pragma unroll
    for(int h=0;h<HH;h++){ den[h]=0.f; y[h]=make_float4(0.f,0.f,0.f,0.f); }

    for(int t=e0; t<e1; t++){
        int s = g_srcs[t];
        float4 xv = x4[(size_t)s*32 + lane];
        const float* sc = &g_score[(size_t)t*HH];
        #pragma unroll
        for(int h=0;h<HH;h++){
            float ex = sc[h];             // broadcast load (same addr warp-wide)
            den[h] += ex;
            y[h].x += ex*xv.x;
            y[h].y += ex*xv.y;
            y[h].z += ex*xv.z;
            y[h].w += ex*xv.w;
        }
    }

    size_t base = (size_t)d*PC;
    #pragma unroll
    for(int h=0;h<HH;h++){
        float r = (den[h] > 0.f) ? 1.f/den[h] : 0.f;
        float v0=y[h].x*r, v1=y[h].y*r, v2=y[h].z*r, v3=y[h].w*r;
        int c = h*CC + lane*4;
        __half h0=__float2half(v0), h1=__float2half(v1);
        __half h2=__float2half(v2), h3=__float2half(v3);
        *(__half2*)&g_yh[base+c]   = __half2(h0, h1);
        *(__half2*)&g_yh[base+c+2] = __half2(h2, h3);
        *(__half2*)&g_yl[base+c]   = __half2(
            __float2half(v0-__half2float(h0)), __float2half(v1-__half2float(h1)));
        *(__half2*)&g_yl[base+c+2] = __half2(
            __float2half(v2-__half2float(h2)), __float2half(v3-__half2float(h3)));
    }
}

// ---------------- GEMM B: out = [y|x] @ WB^T, fp16 3-pass hi/lo --------------
// 128x128 tile, 512 threads; K=896 in 28 chunks of 32; double-buffered
// cp.async, 2 CTAs/SM. Pass order Ah*Bl -> Ah*Bh -> Al*Bh keeps Bh live for
// pass 3 (8 LDSM/ks instead of 10). Epilogue C fp32 [128][132] reuses smem.
#define GB_SEG 10240
#define GB_STAGE (4*GB_SEG)          // 40960
#define GB_SMEM (2*GB_STAGE)         // 81920
__global__ __launch_bounds__(512,2) void gemm_b(
    int layer, int parity,
    const float* __restrict__ bs, const float* __restrict__ lg, const float* __restrict__ lb)
{
    extern __shared__ char dsm[];
    __half (*Ah)[40] = (__half(*)[40])(dsm);
    __half (*Al)[40] = (__half(*)[40])(dsm + GB_SEG);
    __half (*Bh)[40] = (__half(*)[40])(dsm + 2*GB_SEG);
    __half (*Bl)[40] = (__half(*)[40])(dsm + 3*GB_SEG);

    const float* xold = parity ? g_xn : g_x;
    float*       xo   = parity ? g_x  : g_xn;
    int row0 = blockIdx.x * 128;
    int tid = threadIdx.x, warp = tid >> 5, lane = tid & 31;
    int wm = warp >> 2, wn = warp & 3;      // 4 x 4
    int wr0 = wm * 32, wc0 = wn * 32;
    int gid = lane >> 2, tig = lane & 3;

    float acc[2][4][4];
    #pragma unroll
    for(int i=0;i<2;i++)
        #pragma unroll
        for(int j=0;j<4;j++)
            #pragma unroll
            for(int t=0;t<4;t++) acc[i][j][t] = 0.f;

    int lr = tid >> 2;              // row 0..127
    int lc = (tid & 3) * 8;         // one 16B slot per thread per array
    unsigned stAh = smem_u32p(&Ah[lr][lc]);
    unsigned stAl = smem_u32p(&Al[lr][lc]);
    unsigned stBh = smem_u32p(&Bh[lr][lc]);
    unsigned stBl = smem_u32p(&Bl[lr][lc]);

    unsigned aAddrH[2], aAddrL[2], bAddrH[2], bAddrL[2];
    {
        int arow = lane & 15, ak = (lane >> 4) * 8;
        #pragma unroll
        for(int i=0;i<2;i++){
            aAddrH[i] = smem_u32p(&Ah[wr0 + i*16 + arow][ak]);
            aAddrL[i] = smem_u32p(&Al[wr0 + i*16 + arow][ak]);
        }
        int bcol = (lane & 7) + ((lane >> 4) << 3);
        int bk = ((lane >> 3) & 1) * 8;
        #pragma unroll
        for(int g=0; g<2; g++){
            bAddrH[g] = smem_u32p(&Bh[wc0 + g*16 + bcol][bk]);
            bAddrL[g] = smem_u32p(&Bl[wc0 + g*16 + bcol][bk]);
        }
    }

    auto issue = [&](int s){
        int k0 = s * 32;
        unsigned so = (unsigned)(s & 1) * GB_STAGE;
        const __half *ah, *al;
        if(k0 < PC){
            ah = &g_yh[(size_t)(row0+lr)*PC + k0 + lc];
            al = &g_yl[(size_t)(row0+lr)*PC + k0 + lc];
        } else {
            ah = &g_xh[(size_t)(row0+lr)*CC + (k0 - PC) + lc];
            al = &g_xl[(size_t)(row0+lr)*CC + (k0 - PC) + lc];
        }
        const __half* bhg = &g_WBh[((size_t)layer*CC + lr)*KB + k0 + lc];
        const __half* blg = &g_WBl[((size_t)layer*CC + lr)*KB + k0 + lc];
        CPASYNC16(stAh + so, ah);
        CPASYNC16(stAl + so, al);
        CPASYNC16(stBh + so, bhg);
        CPASYNC16(stBl + so, blg);
        CPCOMMIT();
    };

    issue(0);
    for(int s=0; s<28; s++){
        CPWAIT(0);
        __syncthreads();
        if(s < 27) issue(s+1);
        unsigned bo = (unsigned)(s & 1) * GB_STAGE;

        #pragma unroll
        for(int ks=0; ks<32; ks+=16){
            unsigned a_[2][4], b_[4][2];
            // pass 1: Ah x Bl
            #pragma unroll
            for(int g=0; g<2; g++)
                LDSM_X4(b_[g*2][0], b_[g*2][1], b_[g*2+1][0], b_[g*2+1][1], bAddrL[g] + bo + ks*2);
            #pragma unroll
            for(int i=0;i<2;i++)
                LDSM_X4(a_[i][0], a_[i][1], a_[i][2], a_[i][3], aAddrH[i] + bo + ks*2);
            #pragma unroll
            for(int i=0;i<2;i++)
                #pragma unroll
                for(int j=0;j<4;j++)
                    MMA16816(acc[i][j], a_[i], b_[j]);
            // pass 2: Ah x Bh (a_ reused)
            #pragma unroll
            for(int g=0; g<2; g++)
                LDSM_X4(b_[g*2][0], b_[g*2][1], b_[g*2+1][0], b_[g*2+1][1], bAddrH[g] + bo + ks*2);
            #pragma unroll
            for(int i=0;i<2;i++)
                #pragma unroll
                for(int j=0;j<4;j++)
                    MMA16816(acc[i][j], a_[i], b_[j]);
            // pass 3: Al x Bh (b_ still holds Bh)
            #pragma unroll
            for(int i=0;i<2;i++)
                LDSM_X4(a_[i][0], a_[i][1], a_[i][2], a_[i][3], aAddrL[i] + bo + ks*2);
            #pragma unroll
            for(int i=0;i<2;i++)
                #pragma unroll
                for(int j=0;j<4;j++)
                    MMA16816(acc[i][j], a_[i], b_[j]);
        }
        __syncthreads();
    }

    // dump accumulators to smem C (stride 132 floats)
    float* Csm = (float*)dsm;
    #pragma unroll
    for(int i=0;i<2;i++){
        int r = wr0 + i*16 + gid;
        #pragma unroll
        for(int j=0;j<4;j++){
            int c = wc0 + j*8 + 2*tig;
            Csm[r*132 + c]       = acc[i][j][0];
            Csm[r*132 + c + 1]   = acc[i][j][1];
            Csm[(r+8)*132 + c]   = acc[i][j][2];
            Csm[(r+8)*132 + c+1] = acc[i][j][3];
        }
    }
    __syncthreads();

    // epilogue: 4 threads per row, 32 channels each
    {
        int row = tid >> 2, part = tid & 3;
        int n = row0 + row;
        float* Crow = Csm + row*132 + part*32;
        float flag = (g_off[n+1] > g_off[n]) ? 1.f : 0.f;
        const float* xr = &xold[(size_t)n*CC + part*32];
        int cb = part*32;
        float s1 = 0.f;
        #pragma unroll 8
        for(int k=0;k<32;k++){
            int c = cb + k;
            float v = Crow[k] + bs[c] + flag*g_bvm[layer*CC + c] + xr[k];
            Crow[k] = v;
            s1 += v;
        }
        s1 += __shfl_xor_sync(0xffffffffu, s1, 1);
        s1 += __shfl_xor_sync(0xffffffffu, s1, 2);
        float mean = s1 * (1.f/CC);
        float s2 = 0.f;
        #pragma unroll 8
        for(int k=0;k<32;k++){ float dv = Crow[k]-mean; s2 += dv*dv; }
        s2 += __shfl_xor_sync(0xffffffffu, s2, 1);
        s2 += __shfl_xor_sync(0xffffffffu, s2, 2);
        float inv = rsqrtf(s2*(1.f/CC) + 1e-5f);
        #pragma unroll 4
        for(int k=0;k<32;k+=2){
            int c = cb + k;
            float y0 = (Crow[k]  -mean)*inv*lg[c]   + lb[c];
            float y1 = (Crow[k+1]-mean)*inv*lg[c+1] + lb[c+1];
            y0 = fmaxf(y0, 0.f); y1 = fmaxf(y1, 0.f);
            *(float2*)&xo[(size_t)n*CC + c] = make_float2(y0, y1);
            __half h0 = __float2half(y0), h1 = __float2half(y1);
            *(__half2*)&g_xh[(size_t)n*CC + c] = __half2(h0, h1);
            *(__half2*)&g_xl[(size_t)n*CC + c] = __half2(
                __float2half(y0 - __half2float(h0)),
                __float2half(y1 - __half2float(h1)));
        }
    }
}

// ---------------- output MLP on supernodes -----------------------------------
__global__ void mlp_kernel(int sel, const float* __restrict__ W, const float* __restrict__ b){
    const float* in  = sel ? g_m1 : g_x;
    float*       out = sel ? g_m2 : g_m1;
    __shared__ float row[CC];
    int g = blockIdx.x, c = threadIdx.x;
    row[c] = in[(size_t)g*CC + c];
    __syncthreads();
    float acc = b[c];
    const float* w = &W[(size_t)c*CC];
    #pragma unroll 8
    for(int k2=0;k2<CC;k2++) acc += row[k2]*w[k2];
    out[(size_t)g*CC + c] = fmaxf(acc, 0.f);
}

__global__ void final_kernel(const float* __restrict__ Wp, const float* __restrict__ bp,
                             float* __restrict__ out){
    int warp = (blockIdx.x*blockDim.x + threadIdx.x) >> 5;
    int lane = threadIdx.x & 31;
    if(warp >= GG) return;
    float a = 0.f;
    #pragma unroll
    for(int i=0;i<4;i++){
        int c = lane + 32*i;
        a += g_m2[(size_t)warp*CC + c] * Wp[c];
    }
    #pragma unroll
    for(int o=16;o>0;o>>=1) a += __shfl_xor_sync(0xffffffffu, a, o);
    if(lane==0) out[warp] = a + bp[0];
}

// ---------------- launch -----------------------------------------------------
extern "C" void kernel_launch(void* const* d_in, const int* in_sizes, int n_in,
                              void* d_out, int out_size)
{
    const int*   atoms = (const int*)d_in[0];
    const int*   ei    = (const int*)d_in[1];
    const int*   src   = ei;
    const int*   dstp  = ei + EE;
    const float* embd  = (const float*)d_in[2];
    const float* Wq    = (const float*)d_in[3];
    const float* bq    = (const float*)d_in[4];
    const float* Wk    = (const float*)d_in[5];
    const float* bk    = (const float*)d_in[6];  (void)bk; // softmax-invariant
    const float* Wv    = (const float*)d_in[7];
    const float* bv    = (const float*)d_in[8];
    const float* Ws    = (const float*)d_in[9];
    const float* bs    = (const float*)d_in[10];
    const float* lg    = (const float*)d_in[11];
    const float* lb    = (const float*)d_in[12];
    const float* Wlin  = (const float*)d_in[13];
    const float* blin  = (const float*)d_in[14];
    const float* Wp    = (const float*)d_in[15];
    const float* bp    = (const float*)d_in[16];
    float* out = (float*)d_out;

    cudaFuncSetAttribute(gemm_p, cudaFuncAttributeMaxDynamicSharedMemorySize, GP_SMEM);
    cudaFuncSetAttribute(gemm_b, cudaFuncAttributeMaxDynamicSharedMemorySize, GB_SMEM);

    // order chosen so my 4th launch is gemm_p(l=0) (ncu target)
    prep_kernel<<<10282, 128>>>(Wq, Wk, Wv, Ws, bq, bv);           // 1
    embed_kernel<<<NN*CC/256, 256>>>(atoms, embd);                 // 2
    hist_kernel<<<EE/256, 256>>>(dstp);                            // 3
    gemm_p<<<dim3(PC/128, NN/128), 512, GP_SMEM>>>(0);             // 4 <- ncu target
    scan1_kernel<<<32, 1024>>>();                                  // 5
    scan2_kernel<<<1, 32>>>();                                     // 6
    scan3_kernel<<<NN/256, 256>>>();                               // 7
    scatter_kernel<<<EE/256, 256>>>(src, dstp);                    // 8
    score_kernel<<<EE*32/256, 256>>>(0);                           // 9
    agg_kernel<<<NN/8, 256>>>(0);                                  // 10
    gemm_b<<<NN/128, 512, GB_SMEM>>>(0, 0, bs, lg, lb);            // 11

    for(int l=1; l<LL; l++){
        int parity = l & 1;
        gemm_p<<<dim3(PC/128, NN/128), 512, GP_SMEM>>>(l);
        score_kernel<<<EE*32/256, 256>>>(parity);
        agg_kernel<<<NN/8, 256>>>(parity);
        gemm_b<<<NN/128, 512, GB_SMEM>>>(l, parity, bs + (size_t)l*CC,
                                         lg + (size_t)l*CC, lb + (size_t)l*CC);
    }

    mlp_kernel<<<GG, CC>>>(0, Wlin,         blin);
    mlp_kernel<<<GG, CC>>>(1, Wlin + CC*CC, blin + CC);
    final_kernel<<<GG*32/256, 256>>>(Wp, bp, out);
}